// round 1
// baseline (speedup 1.0000x reference)
#include <cuda_runtime.h>
#include <math.h>

// ---------------------------------------------------------------------------
// Problem constants
// ---------------------------------------------------------------------------
namespace cfg {
constexpr int B = 2, S = 1024, H = 1024;
constexpr int NH = 8, NKV = 2, D = 128, ROT = 64;
constexpr int E = 64, TK = 8, NG = 8, TG = 4;
constexpr int FI = 512, FSH = 512, CAP = 512;
constexpr int T = B * S;                  // 2048 tokens
constexpr int QKVW = (NH + 2 * NKV) * D;  // 1536
constexpr float EPS = 1e-5f;
constexpr float SCALE = 0.08838834764831843f;  // 128^-0.5
constexpr float THETA = 10000.0f;
}  // namespace cfg

using namespace cfg;

// ---------------------------------------------------------------------------
// Static device scratch (no allocations allowed)
// ---------------------------------------------------------------------------
constexpr size_t N_H      = (size_t)T * H;
constexpr size_t N_QKV    = (size_t)T * QKVW;
constexpr size_t N_Q      = (size_t)T * NH * D;
constexpr size_t N_K      = (size_t)T * NKV * D;
constexpr size_t N_SC     = (size_t)B * NH * S * S;
constexpr size_t N_AOUT   = (size_t)T * NH * D;
constexpr size_t N_H2     = (size_t)T * H;
constexpr size_t N_XT     = (size_t)T * H;
constexpr size_t N_LOG    = (size_t)T * E;
constexpr size_t N_FW     = (size_t)T * TK;
constexpr size_t N_SGU    = (size_t)T * 2 * FSH;
constexpr size_t N_SHACT  = (size_t)T * FSH;
constexpr size_t N_SHARED = (size_t)T * H;
constexpr size_t N_GU     = (size_t)E * CAP * 2 * FI;
constexpr size_t N_ACT    = (size_t)E * CAP * FI;
constexpr size_t N_EO     = (size_t)E * CAP * H;

constexpr size_t OFF_H      = 0;
constexpr size_t OFF_QKV    = OFF_H + N_H;
constexpr size_t OFF_Q      = OFF_QKV + N_QKV;
constexpr size_t OFF_K      = OFF_Q + N_Q;
constexpr size_t OFF_SC     = OFF_K + N_K;
constexpr size_t OFF_AOUT   = OFF_SC + N_SC;
constexpr size_t OFF_H2     = OFF_AOUT + N_AOUT;
constexpr size_t OFF_XT     = OFF_H2 + N_H2;
constexpr size_t OFF_LOG    = OFF_XT + N_XT;
constexpr size_t OFF_FW     = OFF_LOG + N_LOG;
constexpr size_t OFF_SGU    = OFF_FW + N_FW;
constexpr size_t OFF_SHACT  = OFF_SGU + N_SGU;
constexpr size_t OFF_SHARED = OFF_SHACT + N_SHACT;
constexpr size_t OFF_GU     = OFF_SHARED + N_SHARED;
constexpr size_t OFF_ACT    = OFF_GU + N_GU;
constexpr size_t OFF_EO     = OFF_ACT + N_ACT;
constexpr size_t SCRATCH_F  = OFF_EO + N_EO;

__device__ float g_scratch[SCRATCH_F];

__device__ int g_topi[T * TK];
__device__ int g_slotpos[T * TK];
__device__ int g_cnt[E];
__device__ int g_tok[E * CAP];

// ---------------------------------------------------------------------------
// RMSNorm over rows of length `dim`
// ---------------------------------------------------------------------------
__global__ void rmsnorm_kernel(const float* __restrict__ in,
                               const float* __restrict__ w,
                               float* __restrict__ out, int dim) {
  int t = blockIdx.x;
  const float* r = in + (size_t)t * dim;
  float s = 0.f;
  for (int i = threadIdx.x; i < dim; i += 256) {
    float v = r[i];
    s += v * v;
  }
  for (int o = 16; o; o >>= 1) s += __shfl_xor_sync(~0u, s, o);
  __shared__ float red[8];
  if ((threadIdx.x & 31) == 0) red[threadIdx.x >> 5] = s;
  __syncthreads();
  if (threadIdx.x == 0) {
    float tt = 0.f;
    for (int i = 0; i < 8; i++) tt += red[i];
    red[0] = tt;
  }
  __syncthreads();
  float inv = rsqrtf(red[0] / (float)dim + EPS);
  for (int i = threadIdx.x; i < dim; i += 256)
    out[(size_t)t * dim + i] = r[i] * inv * w[i];
}

// ---------------------------------------------------------------------------
// Per-head Q/K RMSNorm + RoPE. grid (T, NH+NKV), block D=128
// ---------------------------------------------------------------------------
__global__ void qknorm_rope_kernel(const float* __restrict__ qkv,
                                   const int* __restrict__ positions,
                                   const float* __restrict__ qn,
                                   const float* __restrict__ kn,
                                   float* __restrict__ qout,
                                   float* __restrict__ kout) {
  int t = blockIdx.x, hh = blockIdx.y, d = threadIdx.x;
  const float* src;
  const float* w;
  float* dst;
  if (hh < NH) {
    src = qkv + (size_t)t * QKVW + hh * D;
    w = qn;
    dst = qout + ((size_t)t * NH + hh) * D;
  } else {
    int kv = hh - NH;
    src = qkv + (size_t)t * QKVW + NH * D + kv * D;
    w = kn;
    dst = kout + ((size_t)t * NKV + kv) * D;
  }
  float v = src[d];
  float s = v * v;
  for (int o = 16; o; o >>= 1) s += __shfl_xor_sync(~0u, s, o);
  __shared__ float red[4];
  if ((d & 31) == 0) red[d >> 5] = s;
  __syncthreads();
  float tot = red[0] + red[1] + red[2] + red[3];
  float nv = v * rsqrtf(tot / (float)D + EPS) * w[d];
  __shared__ float sh[128];
  sh[d] = nv;
  __syncthreads();
  int sidx = t & (S - 1);
  float pos = (float)positions[sidx];
  float res;
  if (d < ROT / 2) {
    float ang = pos * powf(THETA, -(float)d / (float)(ROT / 2));
    res = sh[d] * cosf(ang) - sh[d + ROT / 2] * sinf(ang);
  } else if (d < ROT) {
    int i2 = d - ROT / 2;
    float ang = pos * powf(THETA, -(float)i2 / (float)(ROT / 2));
    res = sh[d] * cosf(ang) + sh[d - ROT / 2] * sinf(ang);
  } else {
    res = nv;
  }
  dst[d] = res;
}

// ---------------------------------------------------------------------------
// Generic tiled fp32 GEMM, 64x64x16, 256 threads, 4x4 per thread.
// mode selects per-z pointer math + epilogue.
// ---------------------------------------------------------------------------
enum GemmMode {
  M_QKV = 0,   // C = A @ B^T + bias
  M_SCORES,    // per (b,h): C = scale * Q @ K^T, causal mask
  M_AV,        // per (b,h): C = attn @ V  (V strided inside qkv buffer)
  M_WO,        // C = resid + A @ B^T
  M_GATE,      // C = A @ B^T
  M_SGU,       // C = A @ B   (NN)
  M_SDN,       // C = A @ B   (NN)
  M_MOEGU,     // per expert: gathered-A @ B (NN), rows < cnt[e]
  M_MOEDN      // per expert: A @ B (NN), rows < cnt[e]
};

struct GemmP {
  int mode;
  const float* A;
  const float* Bm;
  float* C;
  const float* bias;
  const float* resid;
  const int* gidx;
  const int* cnt;
  int M, N, K, lda, ldb, ldc;
  int transB;
};

__global__ __launch_bounds__(256) void gemm_kernel(GemmP p) {
  int z = blockIdx.z;
  const float* Ab = p.A;
  const float* Bb = p.Bm;
  float* Cb = p.C;
  const int* gidx = nullptr;
  int Meff = p.M;

  if (p.mode == M_SCORES) {
    int b = z >> 3, h = z & 7;
    Ab = p.A + ((size_t)(b * S) * NH + h) * D;
    Bb = p.Bm + ((size_t)(b * S) * NKV + (h >> 2)) * D;
    Cb = p.C + (size_t)z * S * S;
  } else if (p.mode == M_AV) {
    int b = z >> 3, h = z & 7;
    Ab = p.A + (size_t)z * S * S;
    Bb = p.Bm + (size_t)(b * S) * QKVW + (size_t)(NH + NKV) * D + (h >> 2) * D;
    Cb = p.C + (size_t)(b * S) * (NH * D) + h * D;
  } else if (p.mode == M_MOEGU) {
    Meff = min(p.cnt[z], CAP);
    gidx = p.gidx + z * CAP;
    Bb = p.Bm + (size_t)z * H * (2 * FI);
    Cb = p.C + (size_t)z * CAP * (2 * FI);
  } else if (p.mode == M_MOEDN) {
    Meff = min(p.cnt[z], CAP);
    Ab = p.A + (size_t)z * CAP * FI;
    Bb = p.Bm + (size_t)z * FI * H;
    Cb = p.C + (size_t)z * CAP * H;
  }

  int m0 = blockIdx.y * 64, n0 = blockIdx.x * 64;
  if (m0 >= Meff) return;

  __shared__ float As[16][68];
  __shared__ float Bs[16][68];
  int tid = threadIdx.x, tx = tid & 15, ty = tid >> 4;
  float acc[4][4] = {};

  for (int k0 = 0; k0 < p.K; k0 += 16) {
#pragma unroll
    for (int l = 0; l < 4; l++) {
      int i = tid + l * 256;
      int row = i >> 4, col = i & 15;
      int gm = m0 + row;
      float v = 0.f;
      if (gm < Meff) {
        const float* ar =
            gidx ? (Ab + (size_t)gidx[gm] * p.lda) : (Ab + (size_t)gm * p.lda);
        v = ar[k0 + col];
      }
      As[col][row] = v;
    }
#pragma unroll
    for (int l = 0; l < 4; l++) {
      int i = tid + l * 256;
      if (p.transB) {
        int col = i >> 4, kk = i & 15;
        Bs[kk][col] = Bb[(size_t)(n0 + col) * p.ldb + (k0 + kk)];
      } else {
        int kk = i >> 6, col = i & 63;
        Bs[kk][col] = Bb[(size_t)(k0 + kk) * p.ldb + (n0 + col)];
      }
    }
    __syncthreads();
#pragma unroll
    for (int kk = 0; kk < 16; kk++) {
      float4 a4 = *(const float4*)(&As[kk][ty * 4]);
      float4 b4 = *(const float4*)(&Bs[kk][tx * 4]);
      float av[4] = {a4.x, a4.y, a4.z, a4.w};
      float bv[4] = {b4.x, b4.y, b4.z, b4.w};
#pragma unroll
      for (int i = 0; i < 4; i++)
#pragma unroll
        for (int j = 0; j < 4; j++) acc[i][j] += av[i] * bv[j];
    }
    __syncthreads();
  }

#pragma unroll
  for (int i = 0; i < 4; i++) {
    int gm = m0 + ty * 4 + i;
    if (gm >= Meff) continue;
#pragma unroll
    for (int j = 0; j < 4; j++) {
      int gn = n0 + tx * 4 + j;
      float v = acc[i][j];
      if (p.mode == M_QKV)
        v += p.bias[gn];
      else if (p.mode == M_WO)
        v += p.resid[(size_t)gm * p.ldc + gn];
      else if (p.mode == M_SCORES)
        v = (gn <= gm) ? v * SCALE : -INFINITY;
      Cb[(size_t)gm * p.ldc + gn] = v;
    }
  }
}

// ---------------------------------------------------------------------------
// Row softmax over S entries (rows already −inf masked)
// ---------------------------------------------------------------------------
__global__ void softmax_kernel(float* __restrict__ sc) {
  size_t row = blockIdx.x;
  float* p = sc + row * (size_t)S;
  __shared__ float red[8];
  float mx = -INFINITY;
  for (int i = threadIdx.x; i < S; i += 256) mx = fmaxf(mx, p[i]);
  for (int o = 16; o; o >>= 1) mx = fmaxf(mx, __shfl_xor_sync(~0u, mx, o));
  if ((threadIdx.x & 31) == 0) red[threadIdx.x >> 5] = mx;
  __syncthreads();
  if (threadIdx.x == 0) {
    float m = red[0];
    for (int i = 1; i < 8; i++) m = fmaxf(m, red[i]);
    red[0] = m;
  }
  __syncthreads();
  mx = red[0];
  __syncthreads();
  float sum = 0.f;
  for (int i = threadIdx.x; i < S; i += 256) {
    float e = expf(p[i] - mx);
    p[i] = e;
    sum += e;
  }
  for (int o = 16; o; o >>= 1) sum += __shfl_xor_sync(~0u, sum, o);
  if ((threadIdx.x & 31) == 0) red[threadIdx.x >> 5] = sum;
  __syncthreads();
  if (threadIdx.x == 0) {
    float t = 0.f;
    for (int i = 0; i < 8; i++) t += red[i];
    red[0] = t;
  }
  __syncthreads();
  float inv = 1.f / red[0];
  for (int i = threadIdx.x; i < S; i += 256) p[i] *= inv;
}

// ---------------------------------------------------------------------------
// Routing: grouped top-k with sigmoid gate. 1 thread / token.
// ---------------------------------------------------------------------------
__global__ void route_kernel(const float* __restrict__ logits,
                             const float* __restrict__ gate_b,
                             int* __restrict__ topi, float* __restrict__ fw) {
  int t = blockIdx.x * blockDim.x + threadIdx.x;
  if (t >= T) return;
  float corr[E];
  const float* lg = logits + (size_t)t * E;
  for (int e = 0; e < E; e++) {
    float s = 1.f / (1.f + expf(-lg[e]));
    corr[e] = s + gate_b[e];
  }
  float grp[NG];
  for (int g = 0; g < NG; g++) {
    float m1 = -INFINITY, m2 = -INFINITY;
    for (int i = 0; i < E / NG; i++) {
      float v = corr[g * (E / NG) + i];
      if (v > m1) {
        m2 = m1;
        m1 = v;
      } else if (v > m2) {
        m2 = v;
      }
    }
    grp[g] = m1 + m2;
  }
  unsigned gsel = 0;
  for (int it = 0; it < TG; it++) {
    float best = -INFINITY;
    int bi = 0;
    for (int g = 0; g < NG; g++)
      if (!((gsel >> g) & 1u) && grp[g] > best) {
        best = grp[g];
        bi = g;
      }
    gsel |= 1u << bi;
  }
  unsigned long long esel = 0ull;
  int sel[TK];
  float ws[TK];
  float wsum = 0.f;
  for (int it = 0; it < TK; it++) {
    float best = -INFINITY;
    int bi = 0;
    for (int e = 0; e < E; e++) {
      if (!((gsel >> (e >> 3)) & 1u)) continue;
      if ((esel >> e) & 1ull) continue;
      if (corr[e] > best) {
        best = corr[e];
        bi = e;
      }
    }
    esel |= 1ull << bi;
    sel[it] = bi;
    float s = corr[bi] - gate_b[bi];  // recover sigmoid value
    ws[it] = s;
    wsum += s;
  }
  float inv = 1.f / wsum;
  for (int j = 0; j < TK; j++) {
    topi[t * TK + j] = sel[j];
    fw[t * TK + j] = ws[j] * inv;  // RSF = 1
  }
}

__global__ void zero_cnt_kernel(int* __restrict__ cnt) {
  if (threadIdx.x < E) cnt[threadIdx.x] = 0;
}

__global__ void assign_kernel(const int* __restrict__ topi,
                              int* __restrict__ cnt, int* __restrict__ tok,
                              int* __restrict__ slotpos) {
  int i = blockIdx.x * blockDim.x + threadIdx.x;
  if (i >= T * TK) return;
  int e = topi[i];
  int p = atomicAdd(&cnt[e], 1);
  if (p < CAP) {
    tok[e * CAP + p] = i / TK;
    slotpos[i] = p;
  } else {
    slotpos[i] = -1;
  }
}

// ---------------------------------------------------------------------------
// SiLU-gate activations
// ---------------------------------------------------------------------------
__global__ void moe_act_kernel(const float* __restrict__ gu,
                               float* __restrict__ act,
                               const int* __restrict__ cnt) {
  size_t idx = (size_t)blockIdx.x * 256 + threadIdx.x;
  if (idx >= (size_t)E * CAP * FI) return;
  int e = (int)(idx / ((size_t)CAP * FI));
  int r = (int)(idx % ((size_t)CAP * FI));
  int c = r / FI, f = r % FI;
  if (c >= min(cnt[e], CAP)) return;
  const float* gr = gu + ((size_t)e * CAP + c) * (2 * FI);
  float g = gr[f], u = gr[FI + f];
  act[((size_t)e * CAP + c) * FI + f] = (g / (1.f + expf(-g))) * u;
}

__global__ void shared_act_kernel(const float* __restrict__ sgu,
                                  float* __restrict__ act) {
  size_t idx = (size_t)blockIdx.x * 256 + threadIdx.x;
  if (idx >= (size_t)T * FSH) return;
  int t = (int)(idx / FSH), f = (int)(idx % FSH);
  const float* gr = sgu + (size_t)t * (2 * FSH);
  float g = gr[f], u = gr[FSH + f];
  act[(size_t)t * FSH + f] = (g / (1.f + expf(-g))) * u;
}

// ---------------------------------------------------------------------------
// Final combine: out = h2 + shared + sum_j eo[e_j, pos_j] * w_j
// ---------------------------------------------------------------------------
__global__ void final_kernel(const float* __restrict__ h2,
                             const float* __restrict__ sh,
                             const float* __restrict__ eo,
                             const int* __restrict__ topi,
                             const int* __restrict__ slotpos,
                             const float* __restrict__ fw,
                             float* __restrict__ out) {
  int t = blockIdx.x;
  int sel_e[TK], sel_p[TK];
  float sel_w[TK];
#pragma unroll
  for (int j = 0; j < TK; j++) {
    sel_e[j] = topi[t * TK + j];
    sel_p[j] = slotpos[t * TK + j];
    sel_w[j] = fw[t * TK + j];
  }
  for (int c = threadIdx.x; c < H; c += 256) {
    float v = h2[(size_t)t * H + c] + sh[(size_t)t * H + c];
#pragma unroll
    for (int j = 0; j < TK; j++) {
      if (sel_p[j] >= 0)
        v += eo[((size_t)sel_e[j] * CAP + sel_p[j]) * H + c] * sel_w[j];
    }
    out[(size_t)t * H + c] = v;
  }
}

// ---------------------------------------------------------------------------
// Host launcher
// ---------------------------------------------------------------------------
extern "C" void kernel_launch(void* const* d_in, const int* in_sizes, int n_in,
                              void* d_out, int out_size) {
  const float* x = (const float*)d_in[0];
  const int* positions = (const int*)d_in[1];
  const float* ln1_w = (const float*)d_in[2];
  const float* ln2_w = (const float*)d_in[3];
  const float* wqkv = (const float*)d_in[4];
  const float* bqkv = (const float*)d_in[5];
  const float* qn_w = (const float*)d_in[6];
  const float* kn_w = (const float*)d_in[7];
  const float* wo = (const float*)d_in[8];
  const float* gate_w = (const float*)d_in[9];
  const float* gate_b = (const float*)d_in[10];
  const float* w_gu = (const float*)d_in[11];
  const float* w_dn = (const float*)d_in[12];
  const float* sw_gu = (const float*)d_in[13];
  const float* sw_dn = (const float*)d_in[14];
  float* out = (float*)d_out;

  float* scr = nullptr;
  cudaGetSymbolAddress((void**)&scr, g_scratch);
  int* topi = nullptr;
  cudaGetSymbolAddress((void**)&topi, g_topi);
  int* slotpos = nullptr;
  cudaGetSymbolAddress((void**)&slotpos, g_slotpos);
  int* cnt = nullptr;
  cudaGetSymbolAddress((void**)&cnt, g_cnt);
  int* tok = nullptr;
  cudaGetSymbolAddress((void**)&tok, g_tok);

  float* bh = scr + OFF_H;
  float* bqkvb = scr + OFF_QKV;
  float* bq = scr + OFF_Q;
  float* bk = scr + OFF_K;
  float* bsc = scr + OFF_SC;
  float* baout = scr + OFF_AOUT;
  float* bh2 = scr + OFF_H2;
  float* bxt = scr + OFF_XT;
  float* blog = scr + OFF_LOG;
  float* bfw = scr + OFF_FW;
  float* bsgu = scr + OFF_SGU;
  float* bshact = scr + OFF_SHACT;
  float* bshared = scr + OFF_SHARED;
  float* bgu = scr + OFF_GU;
  float* bact = scr + OFF_ACT;
  float* beo = scr + OFF_EO;

  // 1. rmsnorm1
  rmsnorm_kernel<<<T, 256>>>(x, ln1_w, bh, H);

  // 2. qkv = h @ wqkv^T + b
  {
    GemmP p{};
    p.mode = M_QKV;
    p.A = bh; p.Bm = wqkv; p.C = bqkvb; p.bias = bqkv;
    p.M = T; p.N = QKVW; p.K = H;
    p.lda = H; p.ldb = H; p.ldc = QKVW; p.transB = 1;
    gemm_kernel<<<dim3(QKVW / 64, T / 64, 1), 256>>>(p);
  }

  // 3. q/k rmsnorm + rope
  qknorm_rope_kernel<<<dim3(T, NH + NKV), 128>>>(bqkvb, positions, qn_w, kn_w,
                                                 bq, bk);

  // 4. scores = scale * q @ k^T with causal mask
  {
    GemmP p{};
    p.mode = M_SCORES;
    p.A = bq; p.Bm = bk; p.C = bsc;
    p.M = S; p.N = S; p.K = D;
    p.lda = NH * D; p.ldb = NKV * D; p.ldc = S; p.transB = 1;
    gemm_kernel<<<dim3(S / 64, S / 64, B * NH), 256>>>(p);
  }

  // 5. softmax
  softmax_kernel<<<B * NH * S, 256>>>(bsc);

  // 6. out = attn @ v
  {
    GemmP p{};
    p.mode = M_AV;
    p.A = bsc; p.Bm = bqkvb; p.C = baout;
    p.M = S; p.N = D; p.K = S;
    p.lda = S; p.ldb = QKVW; p.ldc = NH * D; p.transB = 0;
    gemm_kernel<<<dim3(D / 64, S / 64, B * NH), 256>>>(p);
  }

  // 7. h2 = x + aout @ wo^T
  {
    GemmP p{};
    p.mode = M_WO;
    p.A = baout; p.Bm = wo; p.C = bh2; p.resid = x;
    p.M = T; p.N = H; p.K = NH * D;
    p.lda = NH * D; p.ldb = NH * D; p.ldc = H; p.transB = 1;
    gemm_kernel<<<dim3(H / 64, T / 64, 1), 256>>>(p);
  }

  // 8. rmsnorm2
  rmsnorm_kernel<<<T, 256>>>(bh2, ln2_w, bxt, H);

  // 9. gate logits
  {
    GemmP p{};
    p.mode = M_GATE;
    p.A = bxt; p.Bm = gate_w; p.C = blog;
    p.M = T; p.N = E; p.K = H;
    p.lda = H; p.ldb = H; p.ldc = E; p.transB = 1;
    gemm_kernel<<<dim3(1, T / 64, 1), 256>>>(p);
  }

  // 10. routing
  route_kernel<<<T / 256, 256>>>(blog, gate_b, topi, bfw);
  zero_cnt_kernel<<<1, 64>>>(cnt);
  assign_kernel<<<(T * TK) / 256, 256>>>(topi, cnt, tok, slotpos);

  // 11. expert gu GEMM (gathered rows)
  {
    GemmP p{};
    p.mode = M_MOEGU;
    p.A = bxt; p.Bm = w_gu; p.C = bgu;
    p.gidx = tok; p.cnt = cnt;
    p.M = CAP; p.N = 2 * FI; p.K = H;
    p.lda = H; p.ldb = 2 * FI; p.ldc = 2 * FI; p.transB = 0;
    gemm_kernel<<<dim3((2 * FI) / 64, CAP / 64, E), 256>>>(p);
  }

  // 12. silu * up
  moe_act_kernel<<<(int)(((size_t)E * CAP * FI + 255) / 256), 256>>>(bgu, bact,
                                                                     cnt);

  // 13. expert down GEMM
  {
    GemmP p{};
    p.mode = M_MOEDN;
    p.A = bact; p.Bm = w_dn; p.C = beo;
    p.cnt = cnt;
    p.M = CAP; p.N = H; p.K = FI;
    p.lda = FI; p.ldb = H; p.ldc = H; p.transB = 0;
    gemm_kernel<<<dim3(H / 64, CAP / 64, E), 256>>>(p);
  }

  // 14. shared expert
  {
    GemmP p{};
    p.mode = M_SGU;
    p.A = bxt; p.Bm = sw_gu; p.C = bsgu;
    p.M = T; p.N = 2 * FSH; p.K = H;
    p.lda = H; p.ldb = 2 * FSH; p.ldc = 2 * FSH; p.transB = 0;
    gemm_kernel<<<dim3((2 * FSH) / 64, T / 64, 1), 256>>>(p);
  }
  shared_act_kernel<<<(int)(((size_t)T * FSH + 255) / 256), 256>>>(bsgu,
                                                                   bshact);
  {
    GemmP p{};
    p.mode = M_SDN;
    p.A = bshact; p.Bm = sw_dn; p.C = bshared;
    p.M = T; p.N = H; p.K = FSH;
    p.lda = FSH; p.ldb = H; p.ldc = H; p.transB = 0;
    gemm_kernel<<<dim3(H / 64, T / 64, 1), 256>>>(p);
  }

  // 15. combine
  final_kernel<<<T, 256>>>(bh2, bshared, beo, topi, slotpos, bfw, out);
}

// round 2
// speedup vs baseline: 2.0945x; 2.0945x over previous
#include <cuda_runtime.h>
#include <math.h>
#include <stdint.h>

// ---------------------------------------------------------------------------
// Problem constants
// ---------------------------------------------------------------------------
namespace cfg {
constexpr int B = 2, S = 1024, H = 1024;
constexpr int NH = 8, NKV = 2, D = 128, ROT = 64;
constexpr int E = 64, TK = 8, NG = 8, TG = 4;
constexpr int FI = 512, FSH = 512, CAP = 512;
constexpr int T = B * S;                  // 2048 tokens
constexpr int QKVW = (NH + 2 * NKV) * D;  // 1536
constexpr float EPS = 1e-5f;
constexpr float SCALE = 0.08838834764831843f;  // 128^-0.5
constexpr float THETA = 10000.0f;
}  // namespace cfg

using namespace cfg;

// ---------------------------------------------------------------------------
// Static device scratch (no allocations allowed)
// ---------------------------------------------------------------------------
constexpr size_t N_H      = (size_t)T * H;
constexpr size_t N_QKV    = (size_t)T * QKVW;
constexpr size_t N_Q      = (size_t)T * NH * D;
constexpr size_t N_K      = (size_t)T * NKV * D;
constexpr size_t N_SC     = (size_t)B * NH * S * S;
constexpr size_t N_AOUT   = (size_t)T * NH * D;
constexpr size_t N_H2     = (size_t)T * H;
constexpr size_t N_XT     = (size_t)T * H;
constexpr size_t N_LOG    = (size_t)T * E;
constexpr size_t N_FW     = (size_t)T * TK;
constexpr size_t N_SGU    = (size_t)T * 2 * FSH;
constexpr size_t N_SHACT  = (size_t)T * FSH;
constexpr size_t N_SHARED = (size_t)T * H;
constexpr size_t N_GU     = (size_t)E * CAP * 2 * FI;
constexpr size_t N_ACT    = (size_t)E * CAP * FI;
constexpr size_t N_EO     = (size_t)E * CAP * H;

constexpr size_t OFF_H      = 0;
constexpr size_t OFF_QKV    = OFF_H + N_H;
constexpr size_t OFF_Q      = OFF_QKV + N_QKV;
constexpr size_t OFF_K      = OFF_Q + N_Q;
constexpr size_t OFF_SC     = OFF_K + N_K;
constexpr size_t OFF_AOUT   = OFF_SC + N_SC;
constexpr size_t OFF_H2     = OFF_AOUT + N_AOUT;
constexpr size_t OFF_XT     = OFF_H2 + N_H2;
constexpr size_t OFF_LOG    = OFF_XT + N_XT;
constexpr size_t OFF_FW     = OFF_LOG + N_LOG;
constexpr size_t OFF_SGU    = OFF_FW + N_FW;
constexpr size_t OFF_SHACT  = OFF_SGU + N_SGU;
constexpr size_t OFF_SHARED = OFF_SHACT + N_SHACT;
constexpr size_t OFF_GU     = OFF_SHARED + N_SHARED;
constexpr size_t OFF_ACT    = OFF_GU + N_GU;
constexpr size_t OFF_EO     = OFF_ACT + N_ACT;
constexpr size_t SCRATCH_F  = OFF_EO + N_EO;

__device__ float g_scratch[SCRATCH_F];

__device__ int g_topi[T * TK];
__device__ int g_slotpos[T * TK];
__device__ int g_cnt[E];
__device__ int g_tok[E * CAP];

// ---------------------------------------------------------------------------
// tf32 helpers
// ---------------------------------------------------------------------------
__device__ __forceinline__ uint32_t f2tf32(float v) {
  uint32_t r;
  asm("cvt.rna.tf32.f32 %0, %1;" : "=r"(r) : "f"(v));
  return r;
}

__device__ __forceinline__ void mma_tf32(float c[4], const uint32_t a[4],
                                         const uint32_t b[2]) {
  asm volatile(
      "mma.sync.aligned.m16n8k8.row.col.f32.tf32.tf32.f32 "
      "{%0,%1,%2,%3}, {%4,%5,%6,%7}, {%8,%9}, {%0,%1,%2,%3};\n"
      : "+f"(c[0]), "+f"(c[1]), "+f"(c[2]), "+f"(c[3])
      : "r"(a[0]), "r"(a[1]), "r"(a[2]), "r"(a[3]), "r"(b[0]), "r"(b[1]));
}

// ---------------------------------------------------------------------------
// RMSNorm over rows of length `dim`
// ---------------------------------------------------------------------------
__global__ void rmsnorm_kernel(const float* __restrict__ in,
                               const float* __restrict__ w,
                               float* __restrict__ out, int dim) {
  int t = blockIdx.x;
  const float* r = in + (size_t)t * dim;
  float s = 0.f;
  for (int i = threadIdx.x; i < dim; i += 256) {
    float v = r[i];
    s += v * v;
  }
  for (int o = 16; o; o >>= 1) s += __shfl_xor_sync(~0u, s, o);
  __shared__ float red[8];
  if ((threadIdx.x & 31) == 0) red[threadIdx.x >> 5] = s;
  __syncthreads();
  if (threadIdx.x == 0) {
    float tt = 0.f;
    for (int i = 0; i < 8; i++) tt += red[i];
    red[0] = tt;
  }
  __syncthreads();
  float inv = rsqrtf(red[0] / (float)dim + EPS);
  for (int i = threadIdx.x; i < dim; i += 256)
    out[(size_t)t * dim + i] = r[i] * inv * w[i];
}

// ---------------------------------------------------------------------------
// Per-head Q/K RMSNorm + RoPE. grid (T, NH+NKV), block D=128
// ---------------------------------------------------------------------------
__global__ void qknorm_rope_kernel(const float* __restrict__ qkv,
                                   const int* __restrict__ positions,
                                   const float* __restrict__ qn,
                                   const float* __restrict__ kn,
                                   float* __restrict__ qout,
                                   float* __restrict__ kout) {
  int t = blockIdx.x, hh = blockIdx.y, d = threadIdx.x;
  const float* src;
  const float* w;
  float* dst;
  if (hh < NH) {
    src = qkv + (size_t)t * QKVW + hh * D;
    w = qn;
    dst = qout + ((size_t)t * NH + hh) * D;
  } else {
    int kv = hh - NH;
    src = qkv + (size_t)t * QKVW + NH * D + kv * D;
    w = kn;
    dst = kout + ((size_t)t * NKV + kv) * D;
  }
  float v = src[d];
  float s = v * v;
  for (int o = 16; o; o >>= 1) s += __shfl_xor_sync(~0u, s, o);
  __shared__ float red[4];
  if ((d & 31) == 0) red[d >> 5] = s;
  __syncthreads();
  float tot = red[0] + red[1] + red[2] + red[3];
  float nv = v * rsqrtf(tot / (float)D + EPS) * w[d];
  __shared__ float sh[128];
  sh[d] = nv;
  __syncthreads();
  int sidx = t & (S - 1);
  float pos = (float)positions[sidx];
  float res;
  if (d < ROT / 2) {
    float ang = pos * powf(THETA, -(float)d / (float)(ROT / 2));
    res = sh[d] * cosf(ang) - sh[d + ROT / 2] * sinf(ang);
  } else if (d < ROT) {
    int i2 = d - ROT / 2;
    float ang = pos * powf(THETA, -(float)i2 / (float)(ROT / 2));
    res = sh[d] * cosf(ang) + sh[d - ROT / 2] * sinf(ang);
  } else {
    res = nv;
  }
  dst[d] = res;
}

// ---------------------------------------------------------------------------
// GEMM modes
// ---------------------------------------------------------------------------
enum GemmMode {
  M_QKV = 0,   // C = A @ B^T + bias
  M_SCORES,    // per (b,h): C = scale * Q @ K^T, causal mask
  M_AV,        // per (b,h): C = attn @ V  (V strided inside qkv buffer)
  M_WO,        // C = resid + A @ B^T
  M_GATE,      // C = A @ B^T
  M_SGU,       // C = A @ B   (NN)
  M_SDN,       // C = A @ B   (NN)
  M_MOEGU,     // per expert: gathered-A @ B (NN), rows < cnt[e]
  M_MOEDN      // per expert: A @ B (NN), rows < cnt[e]
};

struct GemmP {
  int mode;
  const float* A;
  const float* Bm;
  float* C;
  const float* bias;
  const float* resid;
  const int* gidx;
  const int* cnt;
  int M, N, K, lda, ldb, ldc;
  int transB;
};

// ---------------------------------------------------------------------------
// Tensor-core tf32 GEMM: 128x64x16 tile, 256 threads (8 warps, 4x2),
// warp tile 32x32 = 2x4 mma.m16n8k8 fragments.
// ---------------------------------------------------------------------------
__global__ __launch_bounds__(256) void gemm_tc(GemmP p) {
  int z = blockIdx.z;
  const float* Ab = p.A;
  const float* Bb = p.Bm;
  float* Cb = p.C;
  const int* gidx = nullptr;
  int Meff = p.M;

  if (p.mode == M_SCORES) {
    int b = z >> 3, h = z & 7;
    Ab = p.A + ((size_t)(b * S) * NH + h) * D;
    Bb = p.Bm + ((size_t)(b * S) * NKV + (h >> 2)) * D;
    Cb = p.C + (size_t)z * S * S;
  } else if (p.mode == M_AV) {
    int b = z >> 3, h = z & 7;
    Ab = p.A + (size_t)z * S * S;
    Bb = p.Bm + (size_t)(b * S) * QKVW + (size_t)(NH + NKV) * D + (h >> 2) * D;
    Cb = p.C + (size_t)(b * S) * (NH * D) + h * D;
  } else if (p.mode == M_MOEGU) {
    Meff = min(p.cnt[z], CAP);
    gidx = p.gidx + z * CAP;
    Bb = p.Bm + (size_t)z * H * (2 * FI);
    Cb = p.C + (size_t)z * CAP * (2 * FI);
  } else if (p.mode == M_MOEDN) {
    Meff = min(p.cnt[z], CAP);
    Ab = p.A + (size_t)z * CAP * FI;
    Bb = p.Bm + (size_t)z * FI * H;
    Cb = p.C + (size_t)z * CAP * H;
  }

  int m0 = blockIdx.y * 128, n0 = blockIdx.x * 64;
  if (m0 >= Meff) return;

  int tid = threadIdx.x;

  // fully-masked causal block: write -inf, skip compute
  if (p.mode == M_SCORES && n0 >= m0 + 128) {
    for (int i = tid; i < 128 * 64; i += 256) {
      int r = i >> 6, c = i & 63;
      Cb[(size_t)(m0 + r) * p.ldc + (n0 + c)] = -INFINITY;
    }
    return;
  }

  __shared__ uint32_t As[16][132];  // [k][m], stride%32==4 -> conflict free
  __shared__ uint32_t Bs[16][68];   // [k][n]

  int lane = tid & 31, wid = tid >> 5;
  int warp_m = wid >> 1, warp_n = wid & 1;
  int gid = lane >> 2, tig = lane & 3;

  float acc[2][4][4];
#pragma unroll
  for (int a = 0; a < 2; a++)
#pragma unroll
    for (int b = 0; b < 4; b++)
#pragma unroll
      for (int c = 0; c < 4; c++) acc[a][b][c] = 0.f;

  for (int k0 = 0; k0 < p.K; k0 += 16) {
    // --- load A tile 128x16 (as [k][m]) ---
#pragma unroll
    for (int l = 0; l < 2; l++) {
      int idx = tid + l * 256;    // 0..511
      int row = idx >> 2;         // 0..127
      int kq = (idx & 3) * 4;     // 0,4,8,12
      int gm = m0 + row;
      float4 v = make_float4(0.f, 0.f, 0.f, 0.f);
      if (gm < Meff) {
        const float* ar =
            gidx ? (Ab + (size_t)gidx[gm] * p.lda) : (Ab + (size_t)gm * p.lda);
        v = *(const float4*)(ar + k0 + kq);
      }
      As[kq + 0][row] = f2tf32(v.x);
      As[kq + 1][row] = f2tf32(v.y);
      As[kq + 2][row] = f2tf32(v.z);
      As[kq + 3][row] = f2tf32(v.w);
    }
    // --- load B tile 64x16 (as [k][n]) ---
    if (p.transB) {
      int n = tid >> 2;           // 0..63
      int kq = (tid & 3) * 4;
      float4 v = *(const float4*)(Bb + (size_t)(n0 + n) * p.ldb + k0 + kq);
      Bs[kq + 0][n] = f2tf32(v.x);
      Bs[kq + 1][n] = f2tf32(v.y);
      Bs[kq + 2][n] = f2tf32(v.z);
      Bs[kq + 3][n] = f2tf32(v.w);
    } else {
      int kk = tid >> 4;          // 0..15
      int nq = (tid & 15) * 4;
      float4 v = *(const float4*)(Bb + (size_t)(k0 + kk) * p.ldb + n0 + nq);
      Bs[kk][nq + 0] = f2tf32(v.x);
      Bs[kk][nq + 1] = f2tf32(v.y);
      Bs[kk][nq + 2] = f2tf32(v.z);
      Bs[kk][nq + 3] = f2tf32(v.w);
    }
    __syncthreads();

#pragma unroll
    for (int ks = 0; ks < 16; ks += 8) {
      uint32_t afr[2][4], bfr[4][2];
#pragma unroll
      for (int mt = 0; mt < 2; mt++) {
        int mrow = warp_m * 32 + mt * 16;
        afr[mt][0] = As[ks + tig][mrow + gid];
        afr[mt][1] = As[ks + tig][mrow + gid + 8];
        afr[mt][2] = As[ks + tig + 4][mrow + gid];
        afr[mt][3] = As[ks + tig + 4][mrow + gid + 8];
      }
#pragma unroll
      for (int nt = 0; nt < 4; nt++) {
        int ncol = warp_n * 32 + nt * 8;
        bfr[nt][0] = Bs[ks + tig][ncol + gid];
        bfr[nt][1] = Bs[ks + tig + 4][ncol + gid];
      }
#pragma unroll
      for (int mt = 0; mt < 2; mt++)
#pragma unroll
        for (int nt = 0; nt < 4; nt++) mma_tf32(acc[mt][nt], afr[mt], bfr[nt]);
    }
    __syncthreads();
  }

  // --- epilogue ---
#pragma unroll
  for (int mt = 0; mt < 2; mt++) {
#pragma unroll
    for (int nt = 0; nt < 4; nt++) {
#pragma unroll
      for (int ee = 0; ee < 4; ee++) {
        int gm = m0 + warp_m * 32 + mt * 16 + gid + (ee >= 2 ? 8 : 0);
        int gn = n0 + warp_n * 32 + nt * 8 + tig * 2 + (ee & 1);
        if (gm >= Meff) continue;
        float v = acc[mt][nt][ee];
        if (p.mode == M_QKV)
          v += p.bias[gn];
        else if (p.mode == M_WO)
          v += p.resid[(size_t)gm * p.ldc + gn];
        else if (p.mode == M_SCORES)
          v = (gn <= gm) ? v * SCALE : -INFINITY;
        Cb[(size_t)gm * p.ldc + gn] = v;
      }
    }
  }
}

// ---------------------------------------------------------------------------
// fp32 SIMT GEMM (kept for the tiny gate GEMM -> exact routing inputs)
// 64x64x16, 256 threads, 4x4 per thread.
// ---------------------------------------------------------------------------
__global__ __launch_bounds__(256) void gemm_kernel(GemmP p) {
  const float* Ab = p.A;
  const float* Bb = p.Bm;
  float* Cb = p.C;
  int Meff = p.M;

  int m0 = blockIdx.y * 64, n0 = blockIdx.x * 64;
  if (m0 >= Meff) return;

  __shared__ float As[16][68];
  __shared__ float Bs[16][68];
  int tid = threadIdx.x, tx = tid & 15, ty = tid >> 4;
  float acc[4][4] = {};

  for (int k0 = 0; k0 < p.K; k0 += 16) {
#pragma unroll
    for (int l = 0; l < 4; l++) {
      int i = tid + l * 256;
      int row = i >> 4, col = i & 15;
      int gm = m0 + row;
      float v = 0.f;
      if (gm < Meff) v = Ab[(size_t)gm * p.lda + k0 + col];
      As[col][row] = v;
    }
#pragma unroll
    for (int l = 0; l < 4; l++) {
      int i = tid + l * 256;
      if (p.transB) {
        int col = i >> 4, kk = i & 15;
        Bs[kk][col] = Bb[(size_t)(n0 + col) * p.ldb + (k0 + kk)];
      } else {
        int kk = i >> 6, col = i & 63;
        Bs[kk][col] = Bb[(size_t)(k0 + kk) * p.ldb + (n0 + col)];
      }
    }
    __syncthreads();
#pragma unroll
    for (int kk = 0; kk < 16; kk++) {
      float4 a4 = *(const float4*)(&As[kk][ty * 4]);
      float4 b4 = *(const float4*)(&Bs[kk][tx * 4]);
      float av[4] = {a4.x, a4.y, a4.z, a4.w};
      float bv[4] = {b4.x, b4.y, b4.z, b4.w};
#pragma unroll
      for (int i = 0; i < 4; i++)
#pragma unroll
        for (int j = 0; j < 4; j++) acc[i][j] += av[i] * bv[j];
    }
    __syncthreads();
  }

#pragma unroll
  for (int i = 0; i < 4; i++) {
    int gm = m0 + ty * 4 + i;
    if (gm >= Meff) continue;
#pragma unroll
    for (int j = 0; j < 4; j++) {
      int gn = n0 + tx * 4 + j;
      Cb[(size_t)gm * p.ldc + gn] = acc[i][j];
    }
  }
}

// ---------------------------------------------------------------------------
// Row softmax over S entries (rows already −inf masked)
// ---------------------------------------------------------------------------
__global__ void softmax_kernel(float* __restrict__ sc) {
  size_t row = blockIdx.x;
  float* p = sc + row * (size_t)S;
  __shared__ float red[8];
  float mx = -INFINITY;
  for (int i = threadIdx.x; i < S; i += 256) mx = fmaxf(mx, p[i]);
  for (int o = 16; o; o >>= 1) mx = fmaxf(mx, __shfl_xor_sync(~0u, mx, o));
  if ((threadIdx.x & 31) == 0) red[threadIdx.x >> 5] = mx;
  __syncthreads();
  if (threadIdx.x == 0) {
    float m = red[0];
    for (int i = 1; i < 8; i++) m = fmaxf(m, red[i]);
    red[0] = m;
  }
  __syncthreads();
  mx = red[0];
  __syncthreads();
  float sum = 0.f;
  for (int i = threadIdx.x; i < S; i += 256) {
    float e = expf(p[i] - mx);
    p[i] = e;
    sum += e;
  }
  for (int o = 16; o; o >>= 1) sum += __shfl_xor_sync(~0u, sum, o);
  if ((threadIdx.x & 31) == 0) red[threadIdx.x >> 5] = sum;
  __syncthreads();
  if (threadIdx.x == 0) {
    float t = 0.f;
    for (int i = 0; i < 8; i++) t += red[i];
    red[0] = t;
  }
  __syncthreads();
  float inv = 1.f / red[0];
  for (int i = threadIdx.x; i < S; i += 256) p[i] *= inv;
}

// ---------------------------------------------------------------------------
// Routing: grouped top-k with sigmoid gate. 1 thread / token.
// ---------------------------------------------------------------------------
__global__ void route_kernel(const float* __restrict__ logits,
                             const float* __restrict__ gate_b,
                             int* __restrict__ topi, float* __restrict__ fw) {
  int t = blockIdx.x * blockDim.x + threadIdx.x;
  if (t >= T) return;
  float corr[E];
  const float* lg = logits + (size_t)t * E;
  for (int e = 0; e < E; e++) {
    float s = 1.f / (1.f + expf(-lg[e]));
    corr[e] = s + gate_b[e];
  }
  float grp[NG];
  for (int g = 0; g < NG; g++) {
    float m1 = -INFINITY, m2 = -INFINITY;
    for (int i = 0; i < E / NG; i++) {
      float v = corr[g * (E / NG) + i];
      if (v > m1) {
        m2 = m1;
        m1 = v;
      } else if (v > m2) {
        m2 = v;
      }
    }
    grp[g] = m1 + m2;
  }
  unsigned gsel = 0;
  for (int it = 0; it < TG; it++) {
    float best = -INFINITY;
    int bi = 0;
    for (int g = 0; g < NG; g++)
      if (!((gsel >> g) & 1u) && grp[g] > best) {
        best = grp[g];
        bi = g;
      }
    gsel |= 1u << bi;
  }
  unsigned long long esel = 0ull;
  int sel[TK];
  float ws[TK];
  float wsum = 0.f;
  for (int it = 0; it < TK; it++) {
    float best = -INFINITY;
    int bi = 0;
    for (int e = 0; e < E; e++) {
      if (!((gsel >> (e >> 3)) & 1u)) continue;
      if ((esel >> e) & 1ull) continue;
      if (corr[e] > best) {
        best = corr[e];
        bi = e;
      }
    }
    esel |= 1ull << bi;
    sel[it] = bi;
    float s = corr[bi] - gate_b[bi];  // recover sigmoid value
    ws[it] = s;
    wsum += s;
  }
  float inv = 1.f / wsum;
  for (int j = 0; j < TK; j++) {
    topi[t * TK + j] = sel[j];
    fw[t * TK + j] = ws[j] * inv;  // RSF = 1
  }
}

__global__ void zero_cnt_kernel(int* __restrict__ cnt) {
  if (threadIdx.x < E) cnt[threadIdx.x] = 0;
}

__global__ void assign_kernel(const int* __restrict__ topi,
                              int* __restrict__ cnt, int* __restrict__ tok,
                              int* __restrict__ slotpos) {
  int i = blockIdx.x * blockDim.x + threadIdx.x;
  if (i >= T * TK) return;
  int e = topi[i];
  int p = atomicAdd(&cnt[e], 1);
  if (p < CAP) {
    tok[e * CAP + p] = i / TK;
    slotpos[i] = p;
  } else {
    slotpos[i] = -1;
  }
}

// ---------------------------------------------------------------------------
// SiLU-gate activations
// ---------------------------------------------------------------------------
__global__ void moe_act_kernel(const float* __restrict__ gu,
                               float* __restrict__ act,
                               const int* __restrict__ cnt) {
  size_t idx = (size_t)blockIdx.x * 256 + threadIdx.x;
  if (idx >= (size_t)E * CAP * FI) return;
  int e = (int)(idx / ((size_t)CAP * FI));
  int r = (int)(idx % ((size_t)CAP * FI));
  int c = r / FI, f = r % FI;
  if (c >= min(cnt[e], CAP)) return;
  const float* gr = gu + ((size_t)e * CAP + c) * (2 * FI);
  float g = gr[f], u = gr[FI + f];
  act[((size_t)e * CAP + c) * FI + f] = (g / (1.f + expf(-g))) * u;
}

__global__ void shared_act_kernel(const float* __restrict__ sgu,
                                  float* __restrict__ act) {
  size_t idx = (size_t)blockIdx.x * 256 + threadIdx.x;
  if (idx >= (size_t)T * FSH) return;
  int t = (int)(idx / FSH), f = (int)(idx % FSH);
  const float* gr = sgu + (size_t)t * (2 * FSH);
  float g = gr[f], u = gr[FSH + f];
  act[(size_t)t * FSH + f] = (g / (1.f + expf(-g))) * u;
}

// ---------------------------------------------------------------------------
// Final combine: out = h2 + shared + sum_j eo[e_j, pos_j] * w_j
// ---------------------------------------------------------------------------
__global__ void final_kernel(const float* __restrict__ h2,
                             const float* __restrict__ sh,
                             const float* __restrict__ eo,
                             const int* __restrict__ topi,
                             const int* __restrict__ slotpos,
                             const float* __restrict__ fw,
                             float* __restrict__ out) {
  int t = blockIdx.x;
  int sel_e[TK], sel_p[TK];
  float sel_w[TK];
#pragma unroll
  for (int j = 0; j < TK; j++) {
    sel_e[j] = topi[t * TK + j];
    sel_p[j] = slotpos[t * TK + j];
    sel_w[j] = fw[t * TK + j];
  }
  for (int c = threadIdx.x; c < H; c += 256) {
    float v = h2[(size_t)t * H + c] + sh[(size_t)t * H + c];
#pragma unroll
    for (int j = 0; j < TK; j++) {
      if (sel_p[j] >= 0)
        v += eo[((size_t)sel_e[j] * CAP + sel_p[j]) * H + c] * sel_w[j];
    }
    out[(size_t)t * H + c] = v;
  }
}

// ---------------------------------------------------------------------------
// Host launcher
// ---------------------------------------------------------------------------
extern "C" void kernel_launch(void* const* d_in, const int* in_sizes, int n_in,
                              void* d_out, int out_size) {
  const float* x = (const float*)d_in[0];
  const int* positions = (const int*)d_in[1];
  const float* ln1_w = (const float*)d_in[2];
  const float* ln2_w = (const float*)d_in[3];
  const float* wqkv = (const float*)d_in[4];
  const float* bqkv = (const float*)d_in[5];
  const float* qn_w = (const float*)d_in[6];
  const float* kn_w = (const float*)d_in[7];
  const float* wo = (const float*)d_in[8];
  const float* gate_w = (const float*)d_in[9];
  const float* gate_b = (const float*)d_in[10];
  const float* w_gu = (const float*)d_in[11];
  const float* w_dn = (const float*)d_in[12];
  const float* sw_gu = (const float*)d_in[13];
  const float* sw_dn = (const float*)d_in[14];
  float* out = (float*)d_out;

  float* scr = nullptr;
  cudaGetSymbolAddress((void**)&scr, g_scratch);
  int* topi = nullptr;
  cudaGetSymbolAddress((void**)&topi, g_topi);
  int* slotpos = nullptr;
  cudaGetSymbolAddress((void**)&slotpos, g_slotpos);
  int* cnt = nullptr;
  cudaGetSymbolAddress((void**)&cnt, g_cnt);
  int* tok = nullptr;
  cudaGetSymbolAddress((void**)&tok, g_tok);

  float* bh = scr + OFF_H;
  float* bqkvb = scr + OFF_QKV;
  float* bq = scr + OFF_Q;
  float* bk = scr + OFF_K;
  float* bsc = scr + OFF_SC;
  float* baout = scr + OFF_AOUT;
  float* bh2 = scr + OFF_H2;
  float* bxt = scr + OFF_XT;
  float* blog = scr + OFF_LOG;
  float* bfw = scr + OFF_FW;
  float* bsgu = scr + OFF_SGU;
  float* bshact = scr + OFF_SHACT;
  float* bshared = scr + OFF_SHARED;
  float* bgu = scr + OFF_GU;
  float* bact = scr + OFF_ACT;
  float* beo = scr + OFF_EO;

  // 1. rmsnorm1
  rmsnorm_kernel<<<T, 256>>>(x, ln1_w, bh, H);

  // 2. qkv = h @ wqkv^T + b
  {
    GemmP p{};
    p.mode = M_QKV;
    p.A = bh; p.Bm = wqkv; p.C = bqkvb; p.bias = bqkv;
    p.M = T; p.N = QKVW; p.K = H;
    p.lda = H; p.ldb = H; p.ldc = QKVW; p.transB = 1;
    gemm_tc<<<dim3(QKVW / 64, T / 128, 1), 256>>>(p);
  }

  // 3. q/k rmsnorm + rope
  qknorm_rope_kernel<<<dim3(T, NH + NKV), 128>>>(bqkvb, positions, qn_w, kn_w,
                                                 bq, bk);

  // 4. scores = scale * q @ k^T with causal mask
  {
    GemmP p{};
    p.mode = M_SCORES;
    p.A = bq; p.Bm = bk; p.C = bsc;
    p.M = S; p.N = S; p.K = D;
    p.lda = NH * D; p.ldb = NKV * D; p.ldc = S; p.transB = 1;
    gemm_tc<<<dim3(S / 64, S / 128, B * NH), 256>>>(p);
  }

  // 5. softmax
  softmax_kernel<<<B * NH * S, 256>>>(bsc);

  // 6. out = attn @ v
  {
    GemmP p{};
    p.mode = M_AV;
    p.A = bsc; p.Bm = bqkvb; p.C = baout;
    p.M = S; p.N = D; p.K = S;
    p.lda = S; p.ldb = QKVW; p.ldc = NH * D; p.transB = 0;
    gemm_tc<<<dim3(D / 64, S / 128, B * NH), 256>>>(p);
  }

  // 7. h2 = x + aout @ wo^T
  {
    GemmP p{};
    p.mode = M_WO;
    p.A = baout; p.Bm = wo; p.C = bh2; p.resid = x;
    p.M = T; p.N = H; p.K = NH * D;
    p.lda = NH * D; p.ldb = NH * D; p.ldc = H; p.transB = 1;
    gemm_tc<<<dim3(H / 64, T / 128, 1), 256>>>(p);
  }

  // 8. rmsnorm2
  rmsnorm_kernel<<<T, 256>>>(bh2, ln2_w, bxt, H);

  // 9. gate logits (exact fp32 -> stable routing)
  {
    GemmP p{};
    p.mode = M_GATE;
    p.A = bxt; p.Bm = gate_w; p.C = blog;
    p.M = T; p.N = E; p.K = H;
    p.lda = H; p.ldb = H; p.ldc = E; p.transB = 1;
    gemm_kernel<<<dim3(1, T / 64, 1), 256>>>(p);
  }

  // 10. routing
  route_kernel<<<T / 256, 256>>>(blog, gate_b, topi, bfw);
  zero_cnt_kernel<<<1, 64>>>(cnt);
  assign_kernel<<<(T * TK) / 256, 256>>>(topi, cnt, tok, slotpos);

  // 11. expert gu GEMM (gathered rows)
  {
    GemmP p{};
    p.mode = M_MOEGU;
    p.A = bxt; p.Bm = w_gu; p.C = bgu;
    p.gidx = tok; p.cnt = cnt;
    p.M = CAP; p.N = 2 * FI; p.K = H;
    p.lda = H; p.ldb = 2 * FI; p.ldc = 2 * FI; p.transB = 0;
    gemm_tc<<<dim3((2 * FI) / 64, CAP / 128, E), 256>>>(p);
  }

  // 12. silu * up
  moe_act_kernel<<<(int)(((size_t)E * CAP * FI + 255) / 256), 256>>>(bgu, bact,
                                                                     cnt);

  // 13. expert down GEMM
  {
    GemmP p{};
    p.mode = M_MOEDN;
    p.A = bact; p.Bm = w_dn; p.C = beo;
    p.cnt = cnt;
    p.M = CAP; p.N = H; p.K = FI;
    p.lda = FI; p.ldb = H; p.ldc = H; p.transB = 0;
    gemm_tc<<<dim3(H / 64, CAP / 128, E), 256>>>(p);
  }

  // 14. shared expert
  {
    GemmP p{};
    p.mode = M_SGU;
    p.A = bxt; p.Bm = sw_gu; p.C = bsgu;
    p.M = T; p.N = 2 * FSH; p.K = H;
    p.lda = H; p.ldb = 2 * FSH; p.ldc = 2 * FSH; p.transB = 0;
    gemm_tc<<<dim3((2 * FSH) / 64, T / 128, 1), 256>>>(p);
  }
  shared_act_kernel<<<(int)(((size_t)T * FSH + 255) / 256), 256>>>(bsgu,
                                                                   bshact);
  {
    GemmP p{};
    p.mode = M_SDN;
    p.A = bshact; p.Bm = sw_dn; p.C = bshared;
    p.M = T; p.N = H; p.K = FSH;
    p.lda = FSH; p.ldb = H; p.ldc = H; p.transB = 0;
    gemm_tc<<<dim3(H / 64, T / 128, 1), 256>>>(p);
  }

  // 15. combine
  final_kernel<<<T, 256>>>(bh2, bshared, beo, topi, slotpos, bfw, out);
}

// round 3
// speedup vs baseline: 2.5935x; 1.2383x over previous
#include <cuda_runtime.h>
#include <math.h>
#include <stdint.h>

// ---------------------------------------------------------------------------
// Problem constants
// ---------------------------------------------------------------------------
namespace cfg {
constexpr int B = 2, S = 1024, H = 1024;
constexpr int NH = 8, NKV = 2, D = 128, ROT = 64;
constexpr int E = 64, TK = 8, NG = 8, TG = 4;
constexpr int FI = 512, FSH = 512, CAP = 512;
constexpr int T = B * S;                  // 2048 tokens
constexpr int QKVW = (NH + 2 * NKV) * D;  // 1536
constexpr float EPS = 1e-5f;
constexpr float SCALE = 0.08838834764831843f;  // 128^-0.5
constexpr float THETA = 10000.0f;
}  // namespace cfg

using namespace cfg;

// ---------------------------------------------------------------------------
// Static device scratch (no allocations allowed)
// ---------------------------------------------------------------------------
constexpr size_t N_H      = (size_t)T * H;
constexpr size_t N_QKV    = (size_t)T * QKVW;
constexpr size_t N_Q      = (size_t)T * NH * D;
constexpr size_t N_K      = (size_t)T * NKV * D;
constexpr size_t N_SC     = (size_t)B * NH * S * S;
constexpr size_t N_AOUT   = (size_t)T * NH * D;
constexpr size_t N_H2     = (size_t)T * H;
constexpr size_t N_XT     = (size_t)T * H;
constexpr size_t N_LOG    = (size_t)T * E;
constexpr size_t N_FW     = (size_t)T * TK;
constexpr size_t N_SGU    = (size_t)T * 2 * FSH;
constexpr size_t N_SHACT  = (size_t)T * FSH;
constexpr size_t N_SHARED = (size_t)T * H;
constexpr size_t N_GU     = (size_t)E * CAP * 2 * FI;
constexpr size_t N_ACT    = (size_t)E * CAP * FI;
constexpr size_t N_EO     = (size_t)E * CAP * H;

constexpr size_t OFF_H      = 0;
constexpr size_t OFF_QKV    = OFF_H + N_H;
constexpr size_t OFF_Q      = OFF_QKV + N_QKV;
constexpr size_t OFF_K      = OFF_Q + N_Q;
constexpr size_t OFF_SC     = OFF_K + N_K;
constexpr size_t OFF_AOUT   = OFF_SC + N_SC;
constexpr size_t OFF_H2     = OFF_AOUT + N_AOUT;
constexpr size_t OFF_XT     = OFF_H2 + N_H2;
constexpr size_t OFF_LOG    = OFF_XT + N_XT;
constexpr size_t OFF_FW     = OFF_LOG + N_LOG;
constexpr size_t OFF_SGU    = OFF_FW + N_FW;
constexpr size_t OFF_SHACT  = OFF_SGU + N_SGU;
constexpr size_t OFF_SHARED = OFF_SHACT + N_SHACT;
constexpr size_t OFF_GU     = OFF_SHARED + N_SHARED;
constexpr size_t OFF_ACT    = OFF_GU + N_GU;
constexpr size_t OFF_EO     = OFF_ACT + N_ACT;
constexpr size_t SCRATCH_F  = OFF_EO + N_EO;

__device__ float g_scratch[SCRATCH_F];

__device__ int g_topi[T * TK];
__device__ int g_slotpos[T * TK];
__device__ int g_cnt[E];
__device__ int g_tok[E * CAP];

// ---------------------------------------------------------------------------
// tf32 / mma helpers
// ---------------------------------------------------------------------------
__device__ __forceinline__ uint32_t f2tf32(float v) {
  uint32_t r;
  asm("cvt.rna.tf32.f32 %0, %1;" : "=r"(r) : "f"(v));
  return r;
}

__device__ __forceinline__ void mma_tf32(float c[4], const uint32_t a[4],
                                         const uint32_t b[2]) {
  asm volatile(
      "mma.sync.aligned.m16n8k8.row.col.f32.tf32.tf32.f32 "
      "{%0,%1,%2,%3}, {%4,%5,%6,%7}, {%8,%9}, {%0,%1,%2,%3};\n"
      : "+f"(c[0]), "+f"(c[1]), "+f"(c[2]), "+f"(c[3])
      : "r"(a[0]), "r"(a[1]), "r"(a[2]), "r"(a[3]), "r"(b[0]), "r"(b[1]));
}

__device__ __forceinline__ void ldsm4(uint32_t r[4], uint32_t saddr) {
  asm volatile(
      "ldmatrix.sync.aligned.m8n8.x4.shared.b16 {%0,%1,%2,%3}, [%4];"
      : "=r"(r[0]), "=r"(r[1]), "=r"(r[2]), "=r"(r[3])
      : "r"(saddr));
}

// ---------------------------------------------------------------------------
// RMSNorm over rows of length `dim`
// ---------------------------------------------------------------------------
__global__ void rmsnorm_kernel(const float* __restrict__ in,
                               const float* __restrict__ w,
                               float* __restrict__ out, int dim) {
  int t = blockIdx.x;
  const float* r = in + (size_t)t * dim;
  float s = 0.f;
  for (int i = threadIdx.x; i < dim; i += 256) {
    float v = r[i];
    s += v * v;
  }
  for (int o = 16; o; o >>= 1) s += __shfl_xor_sync(~0u, s, o);
  __shared__ float red[8];
  if ((threadIdx.x & 31) == 0) red[threadIdx.x >> 5] = s;
  __syncthreads();
  if (threadIdx.x == 0) {
    float tt = 0.f;
    for (int i = 0; i < 8; i++) tt += red[i];
    red[0] = tt;
  }
  __syncthreads();
  float inv = rsqrtf(red[0] / (float)dim + EPS);
  for (int i = threadIdx.x; i < dim; i += 256)
    out[(size_t)t * dim + i] = r[i] * inv * w[i];
}

// ---------------------------------------------------------------------------
// Per-head Q/K RMSNorm + RoPE. grid (T, NH+NKV), block D=128
// ---------------------------------------------------------------------------
__global__ void qknorm_rope_kernel(const float* __restrict__ qkv,
                                   const int* __restrict__ positions,
                                   const float* __restrict__ qn,
                                   const float* __restrict__ kn,
                                   float* __restrict__ qout,
                                   float* __restrict__ kout) {
  int t = blockIdx.x, hh = blockIdx.y, d = threadIdx.x;
  const float* src;
  const float* w;
  float* dst;
  if (hh < NH) {
    src = qkv + (size_t)t * QKVW + hh * D;
    w = qn;
    dst = qout + ((size_t)t * NH + hh) * D;
  } else {
    int kv = hh - NH;
    src = qkv + (size_t)t * QKVW + NH * D + kv * D;
    w = kn;
    dst = kout + ((size_t)t * NKV + kv) * D;
  }
  float v = src[d];
  float s = v * v;
  for (int o = 16; o; o >>= 1) s += __shfl_xor_sync(~0u, s, o);
  __shared__ float red[4];
  if ((d & 31) == 0) red[d >> 5] = s;
  __syncthreads();
  float tot = red[0] + red[1] + red[2] + red[3];
  float nv = v * rsqrtf(tot / (float)D + EPS) * w[d];
  __shared__ float sh[128];
  sh[d] = nv;
  __syncthreads();
  int sidx = t & (S - 1);
  float pos = (float)positions[sidx];
  float res;
  if (d < ROT / 2) {
    float ang = pos * powf(THETA, -(float)d / (float)(ROT / 2));
    res = sh[d] * cosf(ang) - sh[d + ROT / 2] * sinf(ang);
  } else if (d < ROT) {
    int i2 = d - ROT / 2;
    float ang = pos * powf(THETA, -(float)i2 / (float)(ROT / 2));
    res = sh[d] * cosf(ang) + sh[d - ROT / 2] * sinf(ang);
  } else {
    res = nv;
  }
  dst[d] = res;
}

// ---------------------------------------------------------------------------
// GEMM modes
// ---------------------------------------------------------------------------
enum GemmMode {
  M_QKV = 0,   // C = A @ B^T + bias
  M_SCORES,    // per (b,h): C = scale * Q @ K^T, causal (masked part unwritten)
  M_AV,        // per (b,h): C = attn @ V  (V strided inside qkv buffer)
  M_WO,        // C = resid + A @ B^T
  M_GATE,      // C = A @ B^T
  M_SGU,       // C = A @ B   (NN)
  M_SDN,       // C = A @ B   (NN)
  M_MOEGU,     // per expert: gathered-A @ B (NN), rows < cnt[e]
  M_MOEDN      // per expert: A @ B (NN), rows < cnt[e]
};

struct GemmP {
  int mode;
  const float* A;
  const float* Bm;
  float* C;
  const float* bias;
  const float* resid;
  const int* gidx;
  const int* cnt;
  int M, N, K, lda, ldb, ldc;
  int transB;
};

// ---------------------------------------------------------------------------
// Tensor-core tf32 GEMM: 128x128x16 block tile, 256 threads (8 warps 2x4),
// warp tile 64x32 (mt=4, nt=4), double-buffered smem,
// A fragments via ldmatrix.x4 from [m][k] smem (stride 20 words),
// B fragments via scalar LDS from [k][n] smem (stride 136 words).
// ---------------------------------------------------------------------------
constexpr int APAD = 20;
constexpr int BPAD = 136;

__global__ __launch_bounds__(256, 1) void gemm_tc(GemmP p) {
  int z = blockIdx.z;
  const float* Ab = p.A;
  const float* Bb = p.Bm;
  float* Cb = p.C;
  const int* gidx = nullptr;
  int Meff = p.M;

  if (p.mode == M_SCORES) {
    int b = z >> 3, h = z & 7;
    Ab = p.A + ((size_t)(b * S) * NH + h) * D;
    Bb = p.Bm + ((size_t)(b * S) * NKV + (h >> 2)) * D;
    Cb = p.C + (size_t)z * S * S;
  } else if (p.mode == M_AV) {
    int b = z >> 3, h = z & 7;
    Ab = p.A + (size_t)z * S * S;
    Bb = p.Bm + (size_t)(b * S) * QKVW + (size_t)(NH + NKV) * D + (h >> 2) * D;
    Cb = p.C + (size_t)(b * S) * (NH * D) + h * D;
  } else if (p.mode == M_MOEGU) {
    Meff = min(p.cnt[z], CAP);
    gidx = p.gidx + z * CAP;
    Bb = p.Bm + (size_t)z * H * (2 * FI);
    Cb = p.C + (size_t)z * CAP * (2 * FI);
  } else if (p.mode == M_MOEDN) {
    Meff = min(p.cnt[z], CAP);
    Ab = p.A + (size_t)z * CAP * FI;
    Bb = p.Bm + (size_t)z * FI * H;
    Cb = p.C + (size_t)z * CAP * H;
  }

  int m0 = blockIdx.y * 128, n0 = blockIdx.x * 128;
  if (m0 >= Meff) return;
  // fully-masked causal block: nothing to write (softmax zero-fills)
  if (p.mode == M_SCORES && n0 > m0 + 127) return;

  // effective K (AV can stop at the causal boundary)
  int kend = p.K;
  if (p.mode == M_AV) kend = min(p.K, m0 + 128);
  int nk = kend >> 4;

  __shared__ uint32_t As[2][128 * APAD];
  __shared__ uint32_t Bs[2][16 * BPAD];

  int tid = threadIdx.x;
  int lane = tid & 31, wid = tid >> 5;
  int warp_m = wid & 1, warp_n = wid >> 1;  // 2 x 4
  int gid = lane >> 2, tig = lane & 3;

  uint32_t as_base = (uint32_t)__cvta_generic_to_shared(&As[0][0]);
  // per-lane ldmatrix row/col offsets
  int lm_row = (lane & 15);
  int lm_col = (lane >> 4) << 2;

  float acc[4][4][4];
#pragma unroll
  for (int a = 0; a < 4; a++)
#pragma unroll
    for (int b = 0; b < 4; b++)
#pragma unroll
      for (int c = 0; c < 4; c++) acc[a][b][c] = 0.f;

  // ---- global->reg staging ----
  float4 aReg[2];
  float4 bReg[2];

  auto loadA_g = [&](int k0) {
#pragma unroll
    for (int l = 0; l < 2; l++) {
      int idx = tid + l * 256;
      int row = idx >> 2;
      int kq = (idx & 3) * 4;
      int gm = m0 + row;
      float4 v = make_float4(0.f, 0.f, 0.f, 0.f);
      if (gm < Meff) {
        const float* ar =
            gidx ? (Ab + (size_t)gidx[gm] * p.lda) : (Ab + (size_t)gm * p.lda);
        v = *(const float4*)(ar + k0 + kq);
      }
      aReg[l] = v;
    }
  };
  auto loadB_g = [&](int k0) {
#pragma unroll
    for (int l = 0; l < 2; l++) {
      int idx = tid + l * 256;
      if (p.transB) {
        int n = idx & 127;
        int kq = (idx >> 7) * 4;  // 0 or 4 .. (idx>>7 in 0..3)*4
        bReg[l] = *(const float4*)(Bb + (size_t)(n0 + n) * p.ldb + k0 + kq);
      } else {
        int kk = idx >> 5;
        int nq = (idx & 31) * 4;
        bReg[l] = *(const float4*)(Bb + (size_t)(k0 + kk) * p.ldb + n0 + nq);
      }
    }
  };
  auto stsA = [&](int st) {
#pragma unroll
    for (int l = 0; l < 2; l++) {
      int idx = tid + l * 256;
      int row = idx >> 2;
      int kq = (idx & 3) * 4;
      uint32_t* dst = &As[st][row * APAD + kq];
      dst[0] = f2tf32(aReg[l].x);
      dst[1] = f2tf32(aReg[l].y);
      dst[2] = f2tf32(aReg[l].z);
      dst[3] = f2tf32(aReg[l].w);
    }
  };
  auto stsB = [&](int st) {
#pragma unroll
    for (int l = 0; l < 2; l++) {
      int idx = tid + l * 256;
      if (p.transB) {
        int n = idx & 127;
        int kq = (idx >> 7) * 4;
        Bs[st][(kq + 0) * BPAD + n] = f2tf32(bReg[l].x);
        Bs[st][(kq + 1) * BPAD + n] = f2tf32(bReg[l].y);
        Bs[st][(kq + 2) * BPAD + n] = f2tf32(bReg[l].z);
        Bs[st][(kq + 3) * BPAD + n] = f2tf32(bReg[l].w);
      } else {
        int kk = idx >> 5;
        int nq = (idx & 31) * 4;
        uint32_t* dst = &Bs[st][kk * BPAD + nq];
        dst[0] = f2tf32(bReg[l].x);
        dst[1] = f2tf32(bReg[l].y);
        dst[2] = f2tf32(bReg[l].z);
        dst[3] = f2tf32(bReg[l].w);
      }
    }
  };

  // prologue
  loadA_g(0);
  loadB_g(0);
  stsA(0);
  stsB(0);
  __syncthreads();

  int cur = 0;
  for (int it = 0; it < nk; it++) {
    bool has_next = (it + 1) < nk;
    if (has_next) {
      int k0 = (it + 1) << 4;
      loadA_g(k0);
      loadB_g(k0);
    }
    // compute on stage cur
#pragma unroll
    for (int ks = 0; ks < 16; ks += 8) {
      uint32_t afr[4][4];
#pragma unroll
      for (int mt = 0; mt < 4; mt++) {
        int row = warp_m * 64 + mt * 16 + lm_row;
        uint32_t saddr =
            as_base + (uint32_t)(cur * 128 * APAD + row * APAD + ks + lm_col) * 4u;
        ldsm4(afr[mt], saddr);
      }
      uint32_t bfr[4][2];
#pragma unroll
      for (int nt = 0; nt < 4; nt++) {
        int ncol = warp_n * 32 + nt * 8 + gid;
        bfr[nt][0] = Bs[cur][(ks + tig) * BPAD + ncol];
        bfr[nt][1] = Bs[cur][(ks + tig + 4) * BPAD + ncol];
      }
#pragma unroll
      for (int mt = 0; mt < 4; mt++)
#pragma unroll
        for (int nt = 0; nt < 4; nt++) mma_tf32(acc[mt][nt], afr[mt], bfr[nt]);
    }
    if (has_next) {
      stsA(cur ^ 1);
      stsB(cur ^ 1);
    }
    __syncthreads();
    cur ^= 1;
  }

  // --- epilogue ---
#pragma unroll
  for (int mt = 0; mt < 4; mt++) {
#pragma unroll
    for (int nt = 0; nt < 4; nt++) {
#pragma unroll
      for (int ee = 0; ee < 4; ee++) {
        int gm = m0 + warp_m * 64 + mt * 16 + gid + (ee >= 2 ? 8 : 0);
        int gn = n0 + warp_n * 32 + nt * 8 + tig * 2 + (ee & 1);
        if (gm >= Meff) continue;
        float v = acc[mt][nt][ee];
        if (p.mode == M_QKV)
          v += p.bias[gn];
        else if (p.mode == M_WO)
          v += p.resid[(size_t)gm * p.ldc + gn];
        else if (p.mode == M_SCORES) {
          if (gn > gm) continue;  // masked region never read
          v *= SCALE;
        }
        Cb[(size_t)gm * p.ldc + gn] = v;
      }
    }
  }
}

// ---------------------------------------------------------------------------
// fp32 SIMT GEMM (kept for the tiny gate GEMM -> exact routing inputs)
// ---------------------------------------------------------------------------
__global__ __launch_bounds__(256) void gemm_kernel(GemmP p) {
  const float* Ab = p.A;
  const float* Bb = p.Bm;
  float* Cb = p.C;
  int Meff = p.M;

  int m0 = blockIdx.y * 64, n0 = blockIdx.x * 64;
  if (m0 >= Meff) return;

  __shared__ float As[16][68];
  __shared__ float Bs[16][68];
  int tid = threadIdx.x, tx = tid & 15, ty = tid >> 4;
  float acc[4][4] = {};

  for (int k0 = 0; k0 < p.K; k0 += 16) {
#pragma unroll
    for (int l = 0; l < 4; l++) {
      int i = tid + l * 256;
      int row = i >> 4, col = i & 15;
      int gm = m0 + row;
      float v = 0.f;
      if (gm < Meff) v = Ab[(size_t)gm * p.lda + k0 + col];
      As[col][row] = v;
    }
#pragma unroll
    for (int l = 0; l < 4; l++) {
      int i = tid + l * 256;
      if (p.transB) {
        int col = i >> 4, kk = i & 15;
        Bs[kk][col] = Bb[(size_t)(n0 + col) * p.ldb + (k0 + kk)];
      } else {
        int kk = i >> 6, col = i & 63;
        Bs[kk][col] = Bb[(size_t)(k0 + kk) * p.ldb + (n0 + col)];
      }
    }
    __syncthreads();
#pragma unroll
    for (int kk = 0; kk < 16; kk++) {
      float4 a4 = *(const float4*)(&As[kk][ty * 4]);
      float4 b4 = *(const float4*)(&Bs[kk][tx * 4]);
      float av[4] = {a4.x, a4.y, a4.z, a4.w};
      float bv[4] = {b4.x, b4.y, b4.z, b4.w};
#pragma unroll
      for (int i = 0; i < 4; i++)
#pragma unroll
        for (int j = 0; j < 4; j++) acc[i][j] += av[i] * bv[j];
    }
    __syncthreads();
  }

#pragma unroll
  for (int i = 0; i < 4; i++) {
    int gm = m0 + ty * 4 + i;
    if (gm >= Meff) continue;
#pragma unroll
    for (int j = 0; j < 4; j++) {
      int gn = n0 + tx * 4 + j;
      Cb[(size_t)gm * p.ldc + gn] = acc[i][j];
    }
  }
}

// ---------------------------------------------------------------------------
// Row softmax, causal-aware: only i<=q is live; zero-fill i>q.
// ---------------------------------------------------------------------------
__global__ void softmax_kernel(float* __restrict__ sc) {
  size_t row = blockIdx.x;
  int q = (int)(row & (S - 1));
  int len = q + 1;
  float* p = sc + row * (size_t)S;
  __shared__ float red[8];
  float mx = -INFINITY;
  for (int i = threadIdx.x; i < len; i += 256) mx = fmaxf(mx, p[i]);
  for (int o = 16; o; o >>= 1) mx = fmaxf(mx, __shfl_xor_sync(~0u, mx, o));
  if ((threadIdx.x & 31) == 0) red[threadIdx.x >> 5] = mx;
  __syncthreads();
  if (threadIdx.x == 0) {
    float m = red[0];
    for (int i = 1; i < 8; i++) m = fmaxf(m, red[i]);
    red[0] = m;
  }
  __syncthreads();
  mx = red[0];
  __syncthreads();
  float sum = 0.f;
  for (int i = threadIdx.x; i < len; i += 256) {
    float e = expf(p[i] - mx);
    p[i] = e;
    sum += e;
  }
  for (int o = 16; o; o >>= 1) sum += __shfl_xor_sync(~0u, sum, o);
  if ((threadIdx.x & 31) == 0) red[threadIdx.x >> 5] = sum;
  __syncthreads();
  if (threadIdx.x == 0) {
    float t = 0.f;
    for (int i = 0; i < 8; i++) t += red[i];
    red[0] = t;
  }
  __syncthreads();
  float inv = 1.f / red[0];
  for (int i = threadIdx.x; i < len; i += 256) p[i] *= inv;
  for (int i = len + threadIdx.x; i < S; i += 256) p[i] = 0.f;
}

// ---------------------------------------------------------------------------
// Routing: grouped top-k with sigmoid gate. 1 thread / token.
// ---------------------------------------------------------------------------
__global__ void route_kernel(const float* __restrict__ logits,
                             const float* __restrict__ gate_b,
                             int* __restrict__ topi, float* __restrict__ fw) {
  int t = blockIdx.x * blockDim.x + threadIdx.x;
  if (t >= T) return;
  float corr[E];
  const float* lg = logits + (size_t)t * E;
  for (int e = 0; e < E; e++) {
    float s = 1.f / (1.f + expf(-lg[e]));
    corr[e] = s + gate_b[e];
  }
  float grp[NG];
  for (int g = 0; g < NG; g++) {
    float m1 = -INFINITY, m2 = -INFINITY;
    for (int i = 0; i < E / NG; i++) {
      float v = corr[g * (E / NG) + i];
      if (v > m1) {
        m2 = m1;
        m1 = v;
      } else if (v > m2) {
        m2 = v;
      }
    }
    grp[g] = m1 + m2;
  }
  unsigned gsel = 0;
  for (int it = 0; it < TG; it++) {
    float best = -INFINITY;
    int bi = 0;
    for (int g = 0; g < NG; g++)
      if (!((gsel >> g) & 1u) && grp[g] > best) {
        best = grp[g];
        bi = g;
      }
    gsel |= 1u << bi;
  }
  unsigned long long esel = 0ull;
  int sel[TK];
  float ws[TK];
  float wsum = 0.f;
  for (int it = 0; it < TK; it++) {
    float best = -INFINITY;
    int bi = 0;
    for (int e = 0; e < E; e++) {
      if (!((gsel >> (e >> 3)) & 1u)) continue;
      if ((esel >> e) & 1ull) continue;
      if (corr[e] > best) {
        best = corr[e];
        bi = e;
      }
    }
    esel |= 1ull << bi;
    sel[it] = bi;
    float s = corr[bi] - gate_b[bi];  // recover sigmoid value
    ws[it] = s;
    wsum += s;
  }
  float inv = 1.f / wsum;
  for (int j = 0; j < TK; j++) {
    topi[t * TK + j] = sel[j];
    fw[t * TK + j] = ws[j] * inv;  // RSF = 1
  }
}

__global__ void zero_cnt_kernel(int* __restrict__ cnt) {
  if (threadIdx.x < E) cnt[threadIdx.x] = 0;
}

__global__ void assign_kernel(const int* __restrict__ topi,
                              int* __restrict__ cnt, int* __restrict__ tok,
                              int* __restrict__ slotpos) {
  int i = blockIdx.x * blockDim.x + threadIdx.x;
  if (i >= T * TK) return;
  int e = topi[i];
  int p = atomicAdd(&cnt[e], 1);
  if (p < CAP) {
    tok[e * CAP + p] = i / TK;
    slotpos[i] = p;
  } else {
    slotpos[i] = -1;
  }
}

// ---------------------------------------------------------------------------
// SiLU-gate activations
// ---------------------------------------------------------------------------
__global__ void moe_act_kernel(const float* __restrict__ gu,
                               float* __restrict__ act,
                               const int* __restrict__ cnt) {
  size_t idx = (size_t)blockIdx.x * 256 + threadIdx.x;
  if (idx >= (size_t)E * CAP * FI) return;
  int e = (int)(idx / ((size_t)CAP * FI));
  int r = (int)(idx % ((size_t)CAP * FI));
  int c = r / FI, f = r % FI;
  if (c >= min(cnt[e], CAP)) return;
  const float* gr = gu + ((size_t)e * CAP + c) * (2 * FI);
  float g = gr[f], u = gr[FI + f];
  act[((size_t)e * CAP + c) * FI + f] = (g / (1.f + expf(-g))) * u;
}

__global__ void shared_act_kernel(const float* __restrict__ sgu,
                                  float* __restrict__ act) {
  size_t idx = (size_t)blockIdx.x * 256 + threadIdx.x;
  if (idx >= (size_t)T * FSH) return;
  int t = (int)(idx / FSH), f = (int)(idx % FSH);
  const float* gr = sgu + (size_t)t * (2 * FSH);
  float g = gr[f], u = gr[FSH + f];
  act[(size_t)t * FSH + f] = (g / (1.f + expf(-g))) * u;
}

// ---------------------------------------------------------------------------
// Final combine: out = h2 + shared + sum_j eo[e_j, pos_j] * w_j
// ---------------------------------------------------------------------------
__global__ void final_kernel(const float* __restrict__ h2,
                             const float* __restrict__ sh,
                             const float* __restrict__ eo,
                             const int* __restrict__ topi,
                             const int* __restrict__ slotpos,
                             const float* __restrict__ fw,
                             float* __restrict__ out) {
  int t = blockIdx.x;
  int sel_e[TK], sel_p[TK];
  float sel_w[TK];
#pragma unroll
  for (int j = 0; j < TK; j++) {
    sel_e[j] = topi[t * TK + j];
    sel_p[j] = slotpos[t * TK + j];
    sel_w[j] = fw[t * TK + j];
  }
  for (int c = threadIdx.x; c < H; c += 256) {
    float v = h2[(size_t)t * H + c] + sh[(size_t)t * H + c];
#pragma unroll
    for (int j = 0; j < TK; j++) {
      if (sel_p[j] >= 0)
        v += eo[((size_t)sel_e[j] * CAP + sel_p[j]) * H + c] * sel_w[j];
    }
    out[(size_t)t * H + c] = v;
  }
}

// ---------------------------------------------------------------------------
// Host launcher
// ---------------------------------------------------------------------------
extern "C" void kernel_launch(void* const* d_in, const int* in_sizes, int n_in,
                              void* d_out, int out_size) {
  const float* x = (const float*)d_in[0];
  const int* positions = (const int*)d_in[1];
  const float* ln1_w = (const float*)d_in[2];
  const float* ln2_w = (const float*)d_in[3];
  const float* wqkv = (const float*)d_in[4];
  const float* bqkv = (const float*)d_in[5];
  const float* qn_w = (const float*)d_in[6];
  const float* kn_w = (const float*)d_in[7];
  const float* wo = (const float*)d_in[8];
  const float* gate_w = (const float*)d_in[9];
  const float* gate_b = (const float*)d_in[10];
  const float* w_gu = (const float*)d_in[11];
  const float* w_dn = (const float*)d_in[12];
  const float* sw_gu = (const float*)d_in[13];
  const float* sw_dn = (const float*)d_in[14];
  float* out = (float*)d_out;

  float* scr = nullptr;
  cudaGetSymbolAddress((void**)&scr, g_scratch);
  int* topi = nullptr;
  cudaGetSymbolAddress((void**)&topi, g_topi);
  int* slotpos = nullptr;
  cudaGetSymbolAddress((void**)&slotpos, g_slotpos);
  int* cnt = nullptr;
  cudaGetSymbolAddress((void**)&cnt, g_cnt);
  int* tok = nullptr;
  cudaGetSymbolAddress((void**)&tok, g_tok);

  float* bh = scr + OFF_H;
  float* bqkvb = scr + OFF_QKV;
  float* bq = scr + OFF_Q;
  float* bk = scr + OFF_K;
  float* bsc = scr + OFF_SC;
  float* baout = scr + OFF_AOUT;
  float* bh2 = scr + OFF_H2;
  float* bxt = scr + OFF_XT;
  float* blog = scr + OFF_LOG;
  float* bfw = scr + OFF_FW;
  float* bsgu = scr + OFF_SGU;
  float* bshact = scr + OFF_SHACT;
  float* bshared = scr + OFF_SHARED;
  float* bgu = scr + OFF_GU;
  float* bact = scr + OFF_ACT;
  float* beo = scr + OFF_EO;

  // 1. rmsnorm1
  rmsnorm_kernel<<<T, 256>>>(x, ln1_w, bh, H);

  // 2. qkv = h @ wqkv^T + b
  {
    GemmP p{};
    p.mode = M_QKV;
    p.A = bh; p.Bm = wqkv; p.C = bqkvb; p.bias = bqkv;
    p.M = T; p.N = QKVW; p.K = H;
    p.lda = H; p.ldb = H; p.ldc = QKVW; p.transB = 1;
    gemm_tc<<<dim3(QKVW / 128, T / 128, 1), 256>>>(p);
  }

  // 3. q/k rmsnorm + rope
  qknorm_rope_kernel<<<dim3(T, NH + NKV), 128>>>(bqkvb, positions, qn_w, kn_w,
                                                 bq, bk);

  // 4. scores = scale * q @ k^T (live region only)
  {
    GemmP p{};
    p.mode = M_SCORES;
    p.A = bq; p.Bm = bk; p.C = bsc;
    p.M = S; p.N = S; p.K = D;
    p.lda = NH * D; p.ldb = NKV * D; p.ldc = S; p.transB = 1;
    gemm_tc<<<dim3(S / 128, S / 128, B * NH), 256>>>(p);
  }

  // 5. softmax (causal-aware, zero-fills masked region)
  softmax_kernel<<<B * NH * S, 256>>>(bsc);

  // 6. out = attn @ v
  {
    GemmP p{};
    p.mode = M_AV;
    p.A = bsc; p.Bm = bqkvb; p.C = baout;
    p.M = S; p.N = D; p.K = S;
    p.lda = S; p.ldb = QKVW; p.ldc = NH * D; p.transB = 0;
    gemm_tc<<<dim3(D / 128, S / 128, B * NH), 256>>>(p);
  }

  // 7. h2 = x + aout @ wo^T
  {
    GemmP p{};
    p.mode = M_WO;
    p.A = baout; p.Bm = wo; p.C = bh2; p.resid = x;
    p.M = T; p.N = H; p.K = NH * D;
    p.lda = NH * D; p.ldb = NH * D; p.ldc = H; p.transB = 1;
    gemm_tc<<<dim3(H / 128, T / 128, 1), 256>>>(p);
  }

  // 8. rmsnorm2
  rmsnorm_kernel<<<T, 256>>>(bh2, ln2_w, bxt, H);

  // 9. gate logits (exact fp32 -> stable routing)
  {
    GemmP p{};
    p.mode = M_GATE;
    p.A = bxt; p.Bm = gate_w; p.C = blog;
    p.M = T; p.N = E; p.K = H;
    p.lda = H; p.ldb = H; p.ldc = E; p.transB = 1;
    gemm_kernel<<<dim3(1, T / 64, 1), 256>>>(p);
  }

  // 10. routing
  route_kernel<<<T / 256, 256>>>(blog, gate_b, topi, bfw);
  zero_cnt_kernel<<<1, 64>>>(cnt);
  assign_kernel<<<(T * TK) / 256, 256>>>(topi, cnt, tok, slotpos);

  // 11. expert gu GEMM (gathered rows)
  {
    GemmP p{};
    p.mode = M_MOEGU;
    p.A = bxt; p.Bm = w_gu; p.C = bgu;
    p.gidx = tok; p.cnt = cnt;
    p.M = CAP; p.N = 2 * FI; p.K = H;
    p.lda = H; p.ldb = 2 * FI; p.ldc = 2 * FI; p.transB = 0;
    gemm_tc<<<dim3((2 * FI) / 128, CAP / 128, E), 256>>>(p);
  }

  // 12. silu * up
  moe_act_kernel<<<(int)(((size_t)E * CAP * FI + 255) / 256), 256>>>(bgu, bact,
                                                                     cnt);

  // 13. expert down GEMM
  {
    GemmP p{};
    p.mode = M_MOEDN;
    p.A = bact; p.Bm = w_dn; p.C = beo;
    p.cnt = cnt;
    p.M = CAP; p.N = H; p.K = FI;
    p.lda = FI; p.ldb = H; p.ldc = H; p.transB = 0;
    gemm_tc<<<dim3(H / 128, CAP / 128, E), 256>>>(p);
  }

  // 14. shared expert
  {
    GemmP p{};
    p.mode = M_SGU;
    p.A = bxt; p.Bm = sw_gu; p.C = bsgu;
    p.M = T; p.N = 2 * FSH; p.K = H;
    p.lda = H; p.ldb = 2 * FSH; p.ldc = 2 * FSH; p.transB = 0;
    gemm_tc<<<dim3((2 * FSH) / 128, T / 128, 1), 256>>>(p);
  }
  shared_act_kernel<<<(int)(((size_t)T * FSH + 255) / 256), 256>>>(bsgu,
                                                                   bshact);
  {
    GemmP p{};
    p.mode = M_SDN;
    p.A = bshact; p.Bm = sw_dn; p.C = bshared;
    p.M = T; p.N = H; p.K = FSH;
    p.lda = FSH; p.ldb = H; p.ldc = H; p.transB = 0;
    gemm_tc<<<dim3(H / 128, T / 128, 1), 256>>>(p);
  }

  // 15. combine
  final_kernel<<<T, 256>>>(bh2, bshared, beo, topi, slotpos, bfw, out);
}

// round 4
// speedup vs baseline: 3.8736x; 1.4936x over previous
#include <cuda_runtime.h>
#include <math.h>
#include <stdint.h>

// ---------------------------------------------------------------------------
// Problem constants
// ---------------------------------------------------------------------------
namespace cfg {
constexpr int B = 2, S = 1024, H = 1024;
constexpr int NH = 8, NKV = 2, D = 128, ROT = 64;
constexpr int E = 64, TK = 8, NG = 8, TG = 4;
constexpr int FI = 512, FSH = 512, CAP = 512;
constexpr int T = B * S;                  // 2048 tokens
constexpr int QKVW = (NH + 2 * NKV) * D;  // 1536
constexpr float EPS = 1e-5f;
constexpr float SCALE = 0.08838834764831843f;  // 128^-0.5
constexpr float THETA = 10000.0f;
}  // namespace cfg

using namespace cfg;

// ---------------------------------------------------------------------------
// Static device scratch (no allocations allowed)
// ---------------------------------------------------------------------------
constexpr size_t N_H      = (size_t)T * H;
constexpr size_t N_QKV    = (size_t)T * QKVW;
constexpr size_t N_Q      = (size_t)T * NH * D;
constexpr size_t N_K      = (size_t)T * NKV * D;
constexpr size_t N_SC     = (size_t)B * NH * S * S;
constexpr size_t N_AOUT   = (size_t)T * NH * D;
constexpr size_t N_H2     = (size_t)T * H;
constexpr size_t N_XT     = (size_t)T * H;
constexpr size_t N_LOG    = (size_t)T * E;
constexpr size_t N_FW     = (size_t)T * TK;
constexpr size_t N_SGU    = (size_t)T * 2 * FSH;
constexpr size_t N_SHACT  = (size_t)T * FSH;
constexpr size_t N_SHARED = (size_t)T * H;
constexpr size_t N_GU     = (size_t)E * CAP * 2 * FI;
constexpr size_t N_ACT    = (size_t)E * CAP * FI;
constexpr size_t N_EO     = (size_t)E * CAP * H;

constexpr size_t OFF_H      = 0;
constexpr size_t OFF_QKV    = OFF_H + N_H;
constexpr size_t OFF_Q      = OFF_QKV + N_QKV;
constexpr size_t OFF_K      = OFF_Q + N_Q;
constexpr size_t OFF_SC     = OFF_K + N_K;
constexpr size_t OFF_AOUT   = OFF_SC + N_SC;
constexpr size_t OFF_H2     = OFF_AOUT + N_AOUT;
constexpr size_t OFF_XT     = OFF_H2 + N_H2;
constexpr size_t OFF_LOG    = OFF_XT + N_XT;
constexpr size_t OFF_FW     = OFF_LOG + N_LOG;
constexpr size_t OFF_SGU    = OFF_FW + N_FW;
constexpr size_t OFF_SHACT  = OFF_SGU + N_SGU;
constexpr size_t OFF_SHARED = OFF_SHACT + N_SHACT;
constexpr size_t OFF_GU     = OFF_SHARED + N_SHARED;
constexpr size_t OFF_ACT    = OFF_GU + N_GU;
constexpr size_t OFF_EO     = OFF_ACT + N_ACT;
constexpr size_t SCRATCH_F  = OFF_EO + N_EO;

__device__ float g_scratch[SCRATCH_F];

__device__ int g_topi[T * TK];
__device__ int g_slotpos[T * TK];
__device__ int g_cnt[E];
__device__ int g_tok[E * CAP];

// ---------------------------------------------------------------------------
// mma / cp.async helpers
// ---------------------------------------------------------------------------
__device__ __forceinline__ void mma_tf32(float c[4], const uint32_t a[4],
                                         const uint32_t b[2]) {
  asm volatile(
      "mma.sync.aligned.m16n8k8.row.col.f32.tf32.tf32.f32 "
      "{%0,%1,%2,%3}, {%4,%5,%6,%7}, {%8,%9}, {%0,%1,%2,%3};\n"
      : "+f"(c[0]), "+f"(c[1]), "+f"(c[2]), "+f"(c[3])
      : "r"(a[0]), "r"(a[1]), "r"(a[2]), "r"(a[3]), "r"(b[0]), "r"(b[1]));
}

__device__ __forceinline__ void ldsm4(uint32_t r[4], uint32_t saddr) {
  asm volatile(
      "ldmatrix.sync.aligned.m8n8.x4.shared.b16 {%0,%1,%2,%3}, [%4];"
      : "=r"(r[0]), "=r"(r[1]), "=r"(r[2]), "=r"(r[3])
      : "r"(saddr));
}

__device__ __forceinline__ void cp_async16(uint32_t dst, const void* src,
                                           bool pred) {
  int sz = pred ? 16 : 0;
  asm volatile("cp.async.cg.shared.global [%0], [%1], 16, %2;\n" ::"r"(dst),
               "l"(src), "r"(sz));
}
__device__ __forceinline__ void cp_commit() {
  asm volatile("cp.async.commit_group;\n");
}
template <int N>
__device__ __forceinline__ void cp_wait() {
  asm volatile("cp.async.wait_group %0;\n" ::"n"(N));
}

// ---------------------------------------------------------------------------
// RMSNorm over rows of length `dim`
// ---------------------------------------------------------------------------
__global__ void rmsnorm_kernel(const float* __restrict__ in,
                               const float* __restrict__ w,
                               float* __restrict__ out, int dim) {
  int t = blockIdx.x;
  const float* r = in + (size_t)t * dim;
  float s = 0.f;
  for (int i = threadIdx.x; i < dim; i += 256) {
    float v = r[i];
    s += v * v;
  }
  for (int o = 16; o; o >>= 1) s += __shfl_xor_sync(~0u, s, o);
  __shared__ float red[8];
  if ((threadIdx.x & 31) == 0) red[threadIdx.x >> 5] = s;
  __syncthreads();
  if (threadIdx.x == 0) {
    float tt = 0.f;
    for (int i = 0; i < 8; i++) tt += red[i];
    red[0] = tt;
  }
  __syncthreads();
  float inv = rsqrtf(red[0] / (float)dim + EPS);
  for (int i = threadIdx.x; i < dim; i += 256)
    out[(size_t)t * dim + i] = r[i] * inv * w[i];
}

// ---------------------------------------------------------------------------
// Per-head Q/K RMSNorm + RoPE. grid (T, NH+NKV), block D=128
// ---------------------------------------------------------------------------
__global__ void qknorm_rope_kernel(const float* __restrict__ qkv,
                                   const int* __restrict__ positions,
                                   const float* __restrict__ qn,
                                   const float* __restrict__ kn,
                                   float* __restrict__ qout,
                                   float* __restrict__ kout) {
  int t = blockIdx.x, hh = blockIdx.y, d = threadIdx.x;
  const float* src;
  const float* w;
  float* dst;
  if (hh < NH) {
    src = qkv + (size_t)t * QKVW + hh * D;
    w = qn;
    dst = qout + ((size_t)t * NH + hh) * D;
  } else {
    int kv = hh - NH;
    src = qkv + (size_t)t * QKVW + NH * D + kv * D;
    w = kn;
    dst = kout + ((size_t)t * NKV + kv) * D;
  }
  float v = src[d];
  float s = v * v;
  for (int o = 16; o; o >>= 1) s += __shfl_xor_sync(~0u, s, o);
  __shared__ float red[4];
  if ((d & 31) == 0) red[d >> 5] = s;
  __syncthreads();
  float tot = red[0] + red[1] + red[2] + red[3];
  float nv = v * rsqrtf(tot / (float)D + EPS) * w[d];
  __shared__ float sh[128];
  sh[d] = nv;
  __syncthreads();
  int sidx = t & (S - 1);
  float pos = (float)positions[sidx];
  float res;
  if (d < ROT / 2) {
    float ang = pos * powf(THETA, -(float)d / (float)(ROT / 2));
    res = sh[d] * cosf(ang) - sh[d + ROT / 2] * sinf(ang);
  } else if (d < ROT) {
    int i2 = d - ROT / 2;
    float ang = pos * powf(THETA, -(float)i2 / (float)(ROT / 2));
    res = sh[d] * cosf(ang) + sh[d - ROT / 2] * sinf(ang);
  } else {
    res = nv;
  }
  dst[d] = res;
}

// ---------------------------------------------------------------------------
// GEMM modes
// ---------------------------------------------------------------------------
enum GemmMode {
  M_QKV = 0,   // C = A @ B^T + bias
  M_SCORES,    // per (b,h): C = scale * Q @ K^T, causal (masked part unwritten)
  M_AV,        // per (b,h): C = attn @ V  (V strided inside qkv buffer)
  M_WO,        // C = resid + A @ B^T
  M_GATE,      // C = A @ B^T
  M_SGU,       // C = A @ B   (NN)
  M_SDN,       // C = A @ B   (NN)
  M_MOEGU,     // per expert: gathered-A @ B (NN), rows < cnt[e]
  M_MOEDN      // per expert: A @ B (NN), rows < cnt[e]
};

struct GemmP {
  int mode;
  const float* A;
  const float* Bm;
  float* C;
  const float* bias;
  const float* resid;
  const int* gidx;
  const int* cnt;
  int M, N, K, lda, ldb, ldc;
  int transB;
};

// ---------------------------------------------------------------------------
// Tensor-core tf32 GEMM: 128x128x16 block tile, 256 threads (8 warps 2x4),
// warp tile 64x32, cp.async double-buffered smem, 2 CTAs/SM.
// A smem [m][APAD], ldmatrix.x4.  B smem: transB -> [n][APAD] (scalar LDS),
// NN -> [k][BPAD] (scalar LDS). Raw fp32 bits into tf32 mma (HW truncation).
// ---------------------------------------------------------------------------
constexpr int APAD = 20;   // words; row stride for [m][k] and [n][k] tiles
constexpr int BPAD = 136;  // words; row stride for [k][n] tiles

__global__ __launch_bounds__(256, 2) void gemm_tc(GemmP p) {
  int z = blockIdx.z;
  const float* Ab = p.A;
  const float* Bb = p.Bm;
  float* Cb = p.C;
  const int* gidx = nullptr;
  int Meff = p.M;

  if (p.mode == M_SCORES) {
    int b = z >> 3, h = z & 7;
    Ab = p.A + ((size_t)(b * S) * NH + h) * D;
    Bb = p.Bm + ((size_t)(b * S) * NKV + (h >> 2)) * D;
    Cb = p.C + (size_t)z * S * S;
  } else if (p.mode == M_AV) {
    int b = z >> 3, h = z & 7;
    Ab = p.A + (size_t)z * S * S;
    Bb = p.Bm + (size_t)(b * S) * QKVW + (size_t)(NH + NKV) * D + (h >> 2) * D;
    Cb = p.C + (size_t)(b * S) * (NH * D) + h * D;
  } else if (p.mode == M_MOEGU) {
    Meff = min(p.cnt[z], CAP);
    gidx = p.gidx + z * CAP;
    Bb = p.Bm + (size_t)z * H * (2 * FI);
    Cb = p.C + (size_t)z * CAP * (2 * FI);
  } else if (p.mode == M_MOEDN) {
    Meff = min(p.cnt[z], CAP);
    Ab = p.A + (size_t)z * CAP * FI;
    Bb = p.Bm + (size_t)z * FI * H;
    Cb = p.C + (size_t)z * CAP * H;
  }

  int m0 = blockIdx.y * 128, n0 = blockIdx.x * 128;
  if (m0 >= Meff) return;
  if (p.mode == M_SCORES && n0 > m0 + 127) return;

  int kend = p.K;
  if (p.mode == M_AV) kend = min(p.K, m0 + 128);
  int nk = kend >> 4;

  // per stage: A = 128*APAD = 2560 words, B = max(128*20, 16*136) = 2560 words
  __shared__ uint32_t As[2][128 * APAD];
  __shared__ uint32_t Bs[2][128 * APAD];

  int tid = threadIdx.x;
  int lane = tid & 31, wid = tid >> 5;
  int warp_m = wid & 1, warp_n = wid >> 1;  // 2 x 4
  int gid = lane >> 2, tig = lane & 3;

  uint32_t as_base = (uint32_t)__cvta_generic_to_shared(&As[0][0]);
  uint32_t bs_base = (uint32_t)__cvta_generic_to_shared(&Bs[0][0]);
  int lm_row = (lane & 15);
  int lm_col = (lane >> 4) << 2;

  float acc[4][4][4];
#pragma unroll
  for (int a = 0; a < 4; a++)
#pragma unroll
    for (int b = 0; b < 4; b++)
#pragma unroll
      for (int c = 0; c < 4; c++) acc[a][b][c] = 0.f;

  // precomputed per-thread copy indices
  int a_row0 = tid >> 2, a_kq = (tid & 3) * 4;  // + l*64 rows
  const float* a_src0 = nullptr;
  const float* a_src1 = nullptr;
  {
    int gm0 = m0 + a_row0, gm1 = m0 + a_row0 + 64;
    bool v0 = gm0 < Meff, v1 = gm1 < Meff;
    a_src0 = v0 ? (gidx ? Ab + (size_t)gidx[gm0] * p.lda
                        : Ab + (size_t)gm0 * p.lda)
                : Ab;
    a_src1 = v1 ? (gidx ? Ab + (size_t)gidx[gm1] * p.lda
                        : Ab + (size_t)gm1 * p.lda)
                : Ab;
    // validity folded into size below
  }
  bool a_v0 = (m0 + a_row0) < Meff;
  bool a_v1 = (m0 + a_row0 + 64) < Meff;

  auto issue = [&](int k0, int st) {
    // A: 128 rows x 16 k
    cp_async16(as_base + (uint32_t)(st * 128 * APAD + a_row0 * APAD + a_kq) * 4u,
               a_src0 + k0 + a_kq, a_v0);
    cp_async16(as_base +
                   (uint32_t)(st * 128 * APAD + (a_row0 + 64) * APAD + a_kq) * 4u,
               a_src1 + k0 + a_kq, a_v1);
    // B
    if (p.transB) {
      // [n][k] layout, APAD stride
      int n = tid >> 2, kq = (tid & 3) * 4;
      cp_async16(bs_base + (uint32_t)(st * 128 * APAD + n * APAD + kq) * 4u,
                 Bb + (size_t)(n0 + n) * p.ldb + k0 + kq, true);
      cp_async16(
          bs_base + (uint32_t)(st * 128 * APAD + (n + 64) * APAD + kq) * 4u,
          Bb + (size_t)(n0 + n + 64) * p.ldb + k0 + kq, true);
    } else {
      // [k][n] layout, BPAD stride
      int kk = tid >> 5, nq = (tid & 31) * 4;
      cp_async16(bs_base + (uint32_t)(st * 128 * APAD + kk * BPAD + nq) * 4u,
                 Bb + (size_t)(k0 + kk) * p.ldb + n0 + nq, true);
      cp_async16(
          bs_base + (uint32_t)(st * 128 * APAD + (kk + 8) * BPAD + nq) * 4u,
          Bb + (size_t)(k0 + kk + 8) * p.ldb + n0 + nq, true);
    }
    cp_commit();
  };

  issue(0, 0);

  int cur = 0;
  for (int it = 0; it < nk; it++) {
    if (it + 1 < nk) {
      issue((it + 1) << 4, cur ^ 1);
      cp_wait<1>();
    } else {
      cp_wait<0>();
    }
    __syncthreads();

#pragma unroll
    for (int ks = 0; ks < 16; ks += 8) {
      uint32_t afr[4][4];
#pragma unroll
      for (int mt = 0; mt < 4; mt++) {
        int row = warp_m * 64 + mt * 16 + lm_row;
        uint32_t saddr =
            as_base +
            (uint32_t)(cur * 128 * APAD + row * APAD + ks + lm_col) * 4u;
        ldsm4(afr[mt], saddr);
      }
      uint32_t bfr[4][2];
      if (p.transB) {
#pragma unroll
        for (int nt = 0; nt < 4; nt++) {
          int ncol = warp_n * 32 + nt * 8 + gid;
          bfr[nt][0] = Bs[cur][ncol * APAD + ks + tig];
          bfr[nt][1] = Bs[cur][ncol * APAD + ks + tig + 4];
        }
      } else {
#pragma unroll
        for (int nt = 0; nt < 4; nt++) {
          int ncol = warp_n * 32 + nt * 8 + gid;
          bfr[nt][0] = Bs[cur][(ks + tig) * BPAD + ncol];
          bfr[nt][1] = Bs[cur][(ks + tig + 4) * BPAD + ncol];
        }
      }
#pragma unroll
      for (int mt = 0; mt < 4; mt++)
#pragma unroll
        for (int nt = 0; nt < 4; nt++) mma_tf32(acc[mt][nt], afr[mt], bfr[nt]);
    }
    __syncthreads();
    cur ^= 1;
  }

  // --- epilogue ---
#pragma unroll
  for (int mt = 0; mt < 4; mt++) {
#pragma unroll
    for (int nt = 0; nt < 4; nt++) {
#pragma unroll
      for (int ee = 0; ee < 4; ee++) {
        int gm = m0 + warp_m * 64 + mt * 16 + gid + (ee >= 2 ? 8 : 0);
        int gn = n0 + warp_n * 32 + nt * 8 + tig * 2 + (ee & 1);
        if (gm >= Meff) continue;
        float v = acc[mt][nt][ee];
        if (p.mode == M_QKV)
          v += p.bias[gn];
        else if (p.mode == M_WO)
          v += p.resid[(size_t)gm * p.ldc + gn];
        else if (p.mode == M_SCORES) {
          if (gn > gm) continue;  // masked region never read
          v *= SCALE;
        }
        Cb[(size_t)gm * p.ldc + gn] = v;
      }
    }
  }
}

// ---------------------------------------------------------------------------
// fp32 SIMT GEMM (kept for the tiny gate GEMM -> exact routing inputs)
// ---------------------------------------------------------------------------
__global__ __launch_bounds__(256) void gemm_kernel(GemmP p) {
  const float* Ab = p.A;
  const float* Bb = p.Bm;
  float* Cb = p.C;
  int Meff = p.M;

  int m0 = blockIdx.y * 64, n0 = blockIdx.x * 64;
  if (m0 >= Meff) return;

  __shared__ float As[16][68];
  __shared__ float Bs[16][68];
  int tid = threadIdx.x, tx = tid & 15, ty = tid >> 4;
  float acc[4][4] = {};

  for (int k0 = 0; k0 < p.K; k0 += 16) {
#pragma unroll
    for (int l = 0; l < 4; l++) {
      int i = tid + l * 256;
      int row = i >> 4, col = i & 15;
      int gm = m0 + row;
      float v = 0.f;
      if (gm < Meff) v = Ab[(size_t)gm * p.lda + k0 + col];
      As[col][row] = v;
    }
#pragma unroll
    for (int l = 0; l < 4; l++) {
      int i = tid + l * 256;
      if (p.transB) {
        int col = i >> 4, kk = i & 15;
        Bs[kk][col] = Bb[(size_t)(n0 + col) * p.ldb + (k0 + kk)];
      } else {
        int kk = i >> 6, col = i & 63;
        Bs[kk][col] = Bb[(size_t)(k0 + kk) * p.ldb + (n0 + col)];
      }
    }
    __syncthreads();
#pragma unroll
    for (int kk = 0; kk < 16; kk++) {
      float4 a4 = *(const float4*)(&As[kk][ty * 4]);
      float4 b4 = *(const float4*)(&Bs[kk][tx * 4]);
      float av[4] = {a4.x, a4.y, a4.z, a4.w};
      float bv[4] = {b4.x, b4.y, b4.z, b4.w};
#pragma unroll
      for (int i = 0; i < 4; i++)
#pragma unroll
        for (int j = 0; j < 4; j++) acc[i][j] += av[i] * bv[j];
    }
    __syncthreads();
  }

#pragma unroll
  for (int i = 0; i < 4; i++) {
    int gm = m0 + ty * 4 + i;
    if (gm >= Meff) continue;
#pragma unroll
    for (int j = 0; j < 4; j++) {
      int gn = n0 + tx * 4 + j;
      Cb[(size_t)gm * p.ldc + gn] = acc[i][j];
    }
  }
}

// ---------------------------------------------------------------------------
// Row softmax, causal-aware: only i<=q is live; zero-fill i>q.
// ---------------------------------------------------------------------------
__global__ void softmax_kernel(float* __restrict__ sc) {
  size_t row = blockIdx.x;
  int q = (int)(row & (S - 1));
  int len = q + 1;
  float* p = sc + row * (size_t)S;
  __shared__ float red[8];
  float mx = -INFINITY;
  for (int i = threadIdx.x; i < len; i += 256) mx = fmaxf(mx, p[i]);
  for (int o = 16; o; o >>= 1) mx = fmaxf(mx, __shfl_xor_sync(~0u, mx, o));
  if ((threadIdx.x & 31) == 0) red[threadIdx.x >> 5] = mx;
  __syncthreads();
  if (threadIdx.x == 0) {
    float m = red[0];
    for (int i = 1; i < 8; i++) m = fmaxf(m, red[i]);
    red[0] = m;
  }
  __syncthreads();
  mx = red[0];
  __syncthreads();
  float sum = 0.f;
  for (int i = threadIdx.x; i < len; i += 256) {
    float e = expf(p[i] - mx);
    p[i] = e;
    sum += e;
  }
  for (int o = 16; o; o >>= 1) sum += __shfl_xor_sync(~0u, sum, o);
  if ((threadIdx.x & 31) == 0) red[threadIdx.x >> 5] = sum;
  __syncthreads();
  if (threadIdx.x == 0) {
    float t = 0.f;
    for (int i = 0; i < 8; i++) t += red[i];
    red[0] = t;
  }
  __syncthreads();
  float inv = 1.f / red[0];
  for (int i = threadIdx.x; i < len; i += 256) p[i] *= inv;
  for (int i = len + threadIdx.x; i < S; i += 256) p[i] = 0.f;
}

// ---------------------------------------------------------------------------
// Routing: grouped top-k with sigmoid gate. 1 thread / token.
// ---------------------------------------------------------------------------
__global__ void route_kernel(const float* __restrict__ logits,
                             const float* __restrict__ gate_b,
                             int* __restrict__ topi, float* __restrict__ fw) {
  int t = blockIdx.x * blockDim.x + threadIdx.x;
  if (t >= T) return;
  float corr[E];
  const float* lg = logits + (size_t)t * E;
  for (int e = 0; e < E; e++) {
    float s = 1.f / (1.f + expf(-lg[e]));
    corr[e] = s + gate_b[e];
  }
  float grp[NG];
  for (int g = 0; g < NG; g++) {
    float m1 = -INFINITY, m2 = -INFINITY;
    for (int i = 0; i < E / NG; i++) {
      float v = corr[g * (E / NG) + i];
      if (v > m1) {
        m2 = m1;
        m1 = v;
      } else if (v > m2) {
        m2 = v;
      }
    }
    grp[g] = m1 + m2;
  }
  unsigned gsel = 0;
  for (int it = 0; it < TG; it++) {
    float best = -INFINITY;
    int bi = 0;
    for (int g = 0; g < NG; g++)
      if (!((gsel >> g) & 1u) && grp[g] > best) {
        best = grp[g];
        bi = g;
      }
    gsel |= 1u << bi;
  }
  unsigned long long esel = 0ull;
  int sel[TK];
  float ws[TK];
  float wsum = 0.f;
  for (int it = 0; it < TK; it++) {
    float best = -INFINITY;
    int bi = 0;
    for (int e = 0; e < E; e++) {
      if (!((gsel >> (e >> 3)) & 1u)) continue;
      if ((esel >> e) & 1ull) continue;
      if (corr[e] > best) {
        best = corr[e];
        bi = e;
      }
    }
    esel |= 1ull << bi;
    sel[it] = bi;
    float s = corr[bi] - gate_b[bi];  // recover sigmoid value
    ws[it] = s;
    wsum += s;
  }
  float inv = 1.f / wsum;
  for (int j = 0; j < TK; j++) {
    topi[t * TK + j] = sel[j];
    fw[t * TK + j] = ws[j] * inv;  // RSF = 1
  }
}

__global__ void zero_cnt_kernel(int* __restrict__ cnt) {
  if (threadIdx.x < E) cnt[threadIdx.x] = 0;
}

__global__ void assign_kernel(const int* __restrict__ topi,
                              int* __restrict__ cnt, int* __restrict__ tok,
                              int* __restrict__ slotpos) {
  int i = blockIdx.x * blockDim.x + threadIdx.x;
  if (i >= T * TK) return;
  int e = topi[i];
  int p = atomicAdd(&cnt[e], 1);
  if (p < CAP) {
    tok[e * CAP + p] = i / TK;
    slotpos[i] = p;
  } else {
    slotpos[i] = -1;
  }
}

// ---------------------------------------------------------------------------
// SiLU-gate activations
// ---------------------------------------------------------------------------
__global__ void moe_act_kernel(const float* __restrict__ gu,
                               float* __restrict__ act,
                               const int* __restrict__ cnt) {
  size_t idx = (size_t)blockIdx.x * 256 + threadIdx.x;
  if (idx >= (size_t)E * CAP * FI) return;
  int e = (int)(idx / ((size_t)CAP * FI));
  int r = (int)(idx % ((size_t)CAP * FI));
  int c = r / FI, f = r % FI;
  if (c >= min(cnt[e], CAP)) return;
  const float* gr = gu + ((size_t)e * CAP + c) * (2 * FI);
  float g = gr[f], u = gr[FI + f];
  act[((size_t)e * CAP + c) * FI + f] = (g / (1.f + expf(-g))) * u;
}

__global__ void shared_act_kernel(const float* __restrict__ sgu,
                                  float* __restrict__ act) {
  size_t idx = (size_t)blockIdx.x * 256 + threadIdx.x;
  if (idx >= (size_t)T * FSH) return;
  int t = (int)(idx / FSH), f = (int)(idx % FSH);
  const float* gr = sgu + (size_t)t * (2 * FSH);
  float g = gr[f], u = gr[FSH + f];
  act[(size_t)t * FSH + f] = (g / (1.f + expf(-g))) * u;
}

// ---------------------------------------------------------------------------
// Final combine: out = h2 + shared + sum_j eo[e_j, pos_j] * w_j
// ---------------------------------------------------------------------------
__global__ void final_kernel(const float* __restrict__ h2,
                             const float* __restrict__ sh,
                             const float* __restrict__ eo,
                             const int* __restrict__ topi,
                             const int* __restrict__ slotpos,
                             const float* __restrict__ fw,
                             float* __restrict__ out) {
  int t = blockIdx.x;
  int sel_e[TK], sel_p[TK];
  float sel_w[TK];
#pragma unroll
  for (int j = 0; j < TK; j++) {
    sel_e[j] = topi[t * TK + j];
    sel_p[j] = slotpos[t * TK + j];
    sel_w[j] = fw[t * TK + j];
  }
  for (int c = threadIdx.x; c < H; c += 256) {
    float v = h2[(size_t)t * H + c] + sh[(size_t)t * H + c];
#pragma unroll
    for (int j = 0; j < TK; j++) {
      if (sel_p[j] >= 0)
        v += eo[((size_t)sel_e[j] * CAP + sel_p[j]) * H + c] * sel_w[j];
    }
    out[(size_t)t * H + c] = v;
  }
}

// ---------------------------------------------------------------------------
// Host launcher
// ---------------------------------------------------------------------------
extern "C" void kernel_launch(void* const* d_in, const int* in_sizes, int n_in,
                              void* d_out, int out_size) {
  const float* x = (const float*)d_in[0];
  const int* positions = (const int*)d_in[1];
  const float* ln1_w = (const float*)d_in[2];
  const float* ln2_w = (const float*)d_in[3];
  const float* wqkv = (const float*)d_in[4];
  const float* bqkv = (const float*)d_in[5];
  const float* qn_w = (const float*)d_in[6];
  const float* kn_w = (const float*)d_in[7];
  const float* wo = (const float*)d_in[8];
  const float* gate_w = (const float*)d_in[9];
  const float* gate_b = (const float*)d_in[10];
  const float* w_gu = (const float*)d_in[11];
  const float* w_dn = (const float*)d_in[12];
  const float* sw_gu = (const float*)d_in[13];
  const float* sw_dn = (const float*)d_in[14];
  float* out = (float*)d_out;

  float* scr = nullptr;
  cudaGetSymbolAddress((void**)&scr, g_scratch);
  int* topi = nullptr;
  cudaGetSymbolAddress((void**)&topi, g_topi);
  int* slotpos = nullptr;
  cudaGetSymbolAddress((void**)&slotpos, g_slotpos);
  int* cnt = nullptr;
  cudaGetSymbolAddress((void**)&cnt, g_cnt);
  int* tok = nullptr;
  cudaGetSymbolAddress((void**)&tok, g_tok);

  float* bh = scr + OFF_H;
  float* bqkvb = scr + OFF_QKV;
  float* bq = scr + OFF_Q;
  float* bk = scr + OFF_K;
  float* bsc = scr + OFF_SC;
  float* baout = scr + OFF_AOUT;
  float* bh2 = scr + OFF_H2;
  float* bxt = scr + OFF_XT;
  float* blog = scr + OFF_LOG;
  float* bfw = scr + OFF_FW;
  float* bsgu = scr + OFF_SGU;
  float* bshact = scr + OFF_SHACT;
  float* bshared = scr + OFF_SHARED;
  float* bgu = scr + OFF_GU;
  float* bact = scr + OFF_ACT;
  float* beo = scr + OFF_EO;

  // 1. rmsnorm1
  rmsnorm_kernel<<<T, 256>>>(x, ln1_w, bh, H);

  // 2. qkv = h @ wqkv^T + b
  {
    GemmP p{};
    p.mode = M_QKV;
    p.A = bh; p.Bm = wqkv; p.C = bqkvb; p.bias = bqkv;
    p.M = T; p.N = QKVW; p.K = H;
    p.lda = H; p.ldb = H; p.ldc = QKVW; p.transB = 1;
    gemm_tc<<<dim3(QKVW / 128, T / 128, 1), 256>>>(p);
  }

  // 3. q/k rmsnorm + rope
  qknorm_rope_kernel<<<dim3(T, NH + NKV), 128>>>(bqkvb, positions, qn_w, kn_w,
                                                 bq, bk);

  // 4. scores = scale * q @ k^T (live region only)
  {
    GemmP p{};
    p.mode = M_SCORES;
    p.A = bq; p.Bm = bk; p.C = bsc;
    p.M = S; p.N = S; p.K = D;
    p.lda = NH * D; p.ldb = NKV * D; p.ldc = S; p.transB = 1;
    gemm_tc<<<dim3(S / 128, S / 128, B * NH), 256>>>(p);
  }

  // 5. softmax (causal-aware, zero-fills masked region)
  softmax_kernel<<<B * NH * S, 256>>>(bsc);

  // 6. out = attn @ v
  {
    GemmP p{};
    p.mode = M_AV;
    p.A = bsc; p.Bm = bqkvb; p.C = baout;
    p.M = S; p.N = D; p.K = S;
    p.lda = S; p.ldb = QKVW; p.ldc = NH * D; p.transB = 0;
    gemm_tc<<<dim3(D / 128, S / 128, B * NH), 256>>>(p);
  }

  // 7. h2 = x + aout @ wo^T
  {
    GemmP p{};
    p.mode = M_WO;
    p.A = baout; p.Bm = wo; p.C = bh2; p.resid = x;
    p.M = T; p.N = H; p.K = NH * D;
    p.lda = NH * D; p.ldb = NH * D; p.ldc = H; p.transB = 1;
    gemm_tc<<<dim3(H / 128, T / 128, 1), 256>>>(p);
  }

  // 8. rmsnorm2
  rmsnorm_kernel<<<T, 256>>>(bh2, ln2_w, bxt, H);

  // 9. gate logits (exact fp32 -> stable routing)
  {
    GemmP p{};
    p.mode = M_GATE;
    p.A = bxt; p.Bm = gate_w; p.C = blog;
    p.M = T; p.N = E; p.K = H;
    p.lda = H; p.ldb = H; p.ldc = E; p.transB = 1;
    gemm_kernel<<<dim3(1, T / 64, 1), 256>>>(p);
  }

  // 10. routing
  route_kernel<<<T / 256, 256>>>(blog, gate_b, topi, bfw);
  zero_cnt_kernel<<<1, 64>>>(cnt);
  assign_kernel<<<(T * TK) / 256, 256>>>(topi, cnt, tok, slotpos);

  // 11. expert gu GEMM (gathered rows)
  {
    GemmP p{};
    p.mode = M_MOEGU;
    p.A = bxt; p.Bm = w_gu; p.C = bgu;
    p.gidx = tok; p.cnt = cnt;
    p.M = CAP; p.N = 2 * FI; p.K = H;
    p.lda = H; p.ldb = 2 * FI; p.ldc = 2 * FI; p.transB = 0;
    gemm_tc<<<dim3((2 * FI) / 128, CAP / 128, E), 256>>>(p);
  }

  // 12. silu * up
  moe_act_kernel<<<(int)(((size_t)E * CAP * FI + 255) / 256), 256>>>(bgu, bact,
                                                                     cnt);

  // 13. expert down GEMM
  {
    GemmP p{};
    p.mode = M_MOEDN;
    p.A = bact; p.Bm = w_dn; p.C = beo;
    p.cnt = cnt;
    p.M = CAP; p.N = H; p.K = FI;
    p.lda = FI; p.ldb = H; p.ldc = H; p.transB = 0;
    gemm_tc<<<dim3(H / 128, CAP / 128, E), 256>>>(p);
  }

  // 14. shared expert
  {
    GemmP p{};
    p.mode = M_SGU;
    p.A = bxt; p.Bm = sw_gu; p.C = bsgu;
    p.M = T; p.N = 2 * FSH; p.K = H;
    p.lda = H; p.ldb = 2 * FSH; p.ldc = 2 * FSH; p.transB = 0;
    gemm_tc<<<dim3((2 * FSH) / 128, T / 128, 1), 256>>>(p);
  }
  shared_act_kernel<<<(int)(((size_t)T * FSH + 255) / 256), 256>>>(bsgu,
                                                                   bshact);
  {
    GemmP p{};
    p.mode = M_SDN;
    p.A = bshact; p.Bm = sw_dn; p.C = bshared;
    p.M = T; p.N = H; p.K = FSH;
    p.lda = FSH; p.ldb = H; p.ldc = H; p.transB = 0;
    gemm_tc<<<dim3(H / 128, T / 128, 1), 256>>>(p);
  }

  // 15. combine
  final_kernel<<<T, 256>>>(bh2, bshared, beo, topi, slotpos, bfw, out);
}